// round 1
// baseline (speedup 1.0000x reference)
#include <cuda_runtime.h>

#define N_NODES 50000
#define N_EDGES 800000
#define IN_C 256
#define HID_C 256
#define OUT_C 128

// ---------------- scratch (static device globals; no runtime alloc) ----------
__device__ float g_h1[N_NODES * HID_C];   // x @ W1
__device__ float g_a1[N_NODES * HID_C];   // relu(agg(h1) + b1)
__device__ float g_h2[N_NODES * OUT_C];   // a1 @ W2
__device__ int   g_csr[N_EDGES];          // src node per edge, grouped by dst
__device__ int   g_ptr[N_NODES + 1];
__device__ int   g_cnt[N_NODES];
__device__ int   g_cur[N_NODES];
__device__ float g_dinv[N_NODES];
__device__ int   g_is64;

// ---------------- edge_index dtype detection (int32 vs int64) ----------------
// If int64: high 32-bit word of every element is 0 (values in [0, 50000)).
// If int32: odd words are random node ids -> virtually surely nonzero somewhere.
__global__ void detect_kernel(const unsigned int* __restrict__ w) {
    __shared__ int nz;
    if (threadIdx.x == 0) nz = 0;
    __syncthreads();
    int bad = 0;
    for (int i = threadIdx.x; i < 4096; i += blockDim.x)
        if (w[2 * i + 1] != 0u) bad = 1;
    if (bad) atomicOr(&nz, 1);
    __syncthreads();
    if (threadIdx.x == 0) g_is64 = (nz == 0) ? 1 : 0;
}

__device__ __forceinline__ int edge_at(const void* ei, long long idx) {
    if (g_is64) return (int)((const long long*)ei)[idx];
    return ((const int*)ei)[idx];
}

// ---------------- CSR build --------------------------------------------------
__global__ void zero_kernel() {
    int i = blockIdx.x * blockDim.x + threadIdx.x;
    if (i < N_NODES) { g_cnt[i] = 0; g_cur[i] = 0; }
}

__global__ void count_kernel(const void* __restrict__ ei) {
    int e = blockIdx.x * blockDim.x + threadIdx.x;
    if (e >= N_EDGES) return;
    int c = edge_at(ei, (long long)N_EDGES + e);
    atomicAdd(&g_cnt[c], 1);
}

// single-block exclusive scan of g_cnt -> g_ptr, plus dinv = rsqrt(cnt+1)
__global__ void scan_kernel() {
    __shared__ int sums[1024];
    const int n = N_NODES;
    const int chunk = (n + 1023) / 1024;
    int t = threadIdx.x;
    int start = t * chunk;
    int end = start + chunk; if (end > n) end = n;
    int s = 0;
    for (int i = start; i < end && i < n; i++) s += g_cnt[i];
    sums[t] = s;
    __syncthreads();
    for (int off = 1; off < 1024; off <<= 1) {
        int v = (t >= off) ? sums[t - off] : 0;
        __syncthreads();
        sums[t] += v;
        __syncthreads();
    }
    int run = (t == 0) ? 0 : sums[t - 1];
    for (int i = start; i < end && i < n; i++) {
        int c = g_cnt[i];
        g_ptr[i] = run;
        g_dinv[i] = rsqrtf((float)(c + 1));  // +1 for self-loop; always >= 1
        run += c;
    }
    if (t == 1023) g_ptr[n] = sums[1022];  // total edge count
}

__global__ void fill_kernel(const void* __restrict__ ei) {
    int e = blockIdx.x * blockDim.x + threadIdx.x;
    if (e >= N_EDGES) return;
    int r = edge_at(ei, e);
    int c = edge_at(ei, (long long)N_EDGES + e);
    int pos = g_ptr[c] + atomicAdd(&g_cur[c], 1);
    g_csr[pos] = r;
}

// ---------------- SGEMM: C[M,N] = A[M,K] @ B[K,N] (fp32) ---------------------
#define BM 128
#define BN 64
#define BK 16
#define TM 8
#define TN 4

__global__ __launch_bounds__(256) void sgemm_kernel(
    const float* __restrict__ A, const float* __restrict__ B,
    float* __restrict__ C, int M, int N, int K)
{
    __shared__ __align__(16) float As[BK][BM + 4];
    __shared__ __align__(16) float Bs[BK][BN];

    int tid = threadIdx.x;
    int tx = tid & 15;   // N direction
    int ty = tid >> 4;   // M direction
    int m0 = blockIdx.x * BM;
    int n0 = blockIdx.y * BN;

    float acc[TM][TN];
#pragma unroll
    for (int i = 0; i < TM; i++)
#pragma unroll
        for (int j = 0; j < TN; j++) acc[i][j] = 0.0f;

    for (int k0 = 0; k0 < K; k0 += BK) {
        // load A tile (BM x BK), transposed into As[k][m]
#pragma unroll
        for (int i = 0; i < 2; i++) {
            int idx = tid * 2 + i;          // 0..511 float4 slots
            int fr = idx >> 2;              // row within tile (0..127)
            int fc = idx & 3;               // float4 col within 16
            int m = m0 + fr;
            float4 v = make_float4(0.f, 0.f, 0.f, 0.f);
            if (m < M) v = *(const float4*)(A + (size_t)m * K + k0 + fc * 4);
            As[fc * 4 + 0][fr] = v.x;
            As[fc * 4 + 1][fr] = v.y;
            As[fc * 4 + 2][fr] = v.z;
            As[fc * 4 + 3][fr] = v.w;
        }
        // load B tile (BK x BN)
        {
            int fr = tid >> 4;   // k row 0..15
            int fc = tid & 15;   // float4 col 0..15
            float4 v = *(const float4*)(B + (size_t)(k0 + fr) * N + n0 + fc * 4);
            *(float4*)&Bs[fr][fc * 4] = v;
        }
        __syncthreads();

#pragma unroll
        for (int k = 0; k < BK; k++) {
            float a[TM], b[TN];
            *(float4*)&a[0] = *(const float4*)&As[k][ty * TM];
            *(float4*)&a[4] = *(const float4*)&As[k][ty * TM + 4];
            *(float4*)&b[0] = *(const float4*)&Bs[k][tx * TN];
#pragma unroll
            for (int i = 0; i < TM; i++)
#pragma unroll
                for (int j = 0; j < TN; j++)
                    acc[i][j] += a[i] * b[j];
        }
        __syncthreads();
    }

#pragma unroll
    for (int i = 0; i < TM; i++) {
        int m = m0 + ty * TM + i;
        if (m < M) {
            float4 v = make_float4(acc[i][0], acc[i][1], acc[i][2], acc[i][3]);
            *(float4*)(C + (size_t)m * N + n0 + tx * TN) = v;
        }
    }
}

// ---------------- aggregation ------------------------------------------------
// out[c] = dinv[c] * ( sum_{e: dst=c} dinv[src]*h[src]  +  dinv[c]*h[c] ) + bias
// warp-per-node; channels split across lanes as float4s. Writes coalesced, no atomics.

__device__ __forceinline__ float4 f4_fma(float w, float4 v, float4 a) {
    a.x += w * v.x; a.y += w * v.y; a.z += w * v.z; a.w += w * v.w; return a;
}

__global__ __launch_bounds__(256) void agg256_kernel(
    const float* __restrict__ h, float* __restrict__ out,
    const float* __restrict__ bias)
{
    int warp = (blockIdx.x * blockDim.x + threadIdx.x) >> 5;
    int lane = threadIdx.x & 31;
    if (warp >= N_NODES) return;
    int node = warp;

    const float4* hv = (const float4*)h;   // 64 float4 per row
    int p0 = g_ptr[node], p1 = g_ptr[node + 1];
    float dc = g_dinv[node];

    const float4* selfr = hv + (size_t)node * 64;
    float4 acc0 = f4_fma(dc, selfr[lane],      make_float4(0.f,0.f,0.f,0.f));
    float4 acc1 = f4_fma(dc, selfr[lane + 32], make_float4(0.f,0.f,0.f,0.f));

    int e = p0;
    for (; e + 2 <= p1; e += 2) {
        int s0 = g_csr[e], s1 = g_csr[e + 1];
        float w0 = g_dinv[s0], w1 = g_dinv[s1];
        const float4* r0 = hv + (size_t)s0 * 64;
        const float4* r1 = hv + (size_t)s1 * 64;
        acc0 = f4_fma(w0, r0[lane], acc0);
        acc1 = f4_fma(w0, r0[lane + 32], acc1);
        acc0 = f4_fma(w1, r1[lane], acc0);
        acc1 = f4_fma(w1, r1[lane + 32], acc1);
    }
    if (e < p1) {
        int s0 = g_csr[e];
        float w0 = g_dinv[s0];
        const float4* r0 = hv + (size_t)s0 * 64;
        acc0 = f4_fma(w0, r0[lane], acc0);
        acc1 = f4_fma(w0, r0[lane + 32], acc1);
    }

    float4 b0 = ((const float4*)bias)[lane];
    float4 b1v = ((const float4*)bias)[lane + 32];
    float4 o0, o1;
    o0.x = fmaxf(dc * acc0.x + b0.x, 0.f);
    o0.y = fmaxf(dc * acc0.y + b0.y, 0.f);
    o0.z = fmaxf(dc * acc0.z + b0.z, 0.f);
    o0.w = fmaxf(dc * acc0.w + b0.w, 0.f);
    o1.x = fmaxf(dc * acc1.x + b1v.x, 0.f);
    o1.y = fmaxf(dc * acc1.y + b1v.y, 0.f);
    o1.z = fmaxf(dc * acc1.z + b1v.z, 0.f);
    o1.w = fmaxf(dc * acc1.w + b1v.w, 0.f);

    float4* ov = (float4*)out + (size_t)node * 64;
    ov[lane] = o0;
    ov[lane + 32] = o1;
}

__global__ __launch_bounds__(256) void agg128_kernel(
    const float* __restrict__ h, float* __restrict__ out,
    const float* __restrict__ bias)
{
    int warp = (blockIdx.x * blockDim.x + threadIdx.x) >> 5;
    int lane = threadIdx.x & 31;
    if (warp >= N_NODES) return;
    int node = warp;

    const float4* hv = (const float4*)h;   // 32 float4 per row
    int p0 = g_ptr[node], p1 = g_ptr[node + 1];
    float dc = g_dinv[node];

    const float4* selfr = hv + (size_t)node * 32;
    float4 acc = f4_fma(dc, selfr[lane], make_float4(0.f,0.f,0.f,0.f));

    int e = p0;
    for (; e + 2 <= p1; e += 2) {
        int s0 = g_csr[e], s1 = g_csr[e + 1];
        float w0 = g_dinv[s0], w1 = g_dinv[s1];
        const float4* r0 = hv + (size_t)s0 * 32;
        const float4* r1 = hv + (size_t)s1 * 32;
        acc = f4_fma(w0, r0[lane], acc);
        acc = f4_fma(w1, r1[lane], acc);
    }
    if (e < p1) {
        int s0 = g_csr[e];
        float w0 = g_dinv[s0];
        acc = f4_fma(w0, (hv + (size_t)s0 * 32)[lane], acc);
    }

    float4 b0 = ((const float4*)bias)[lane];
    float4 o;
    o.x = dc * acc.x + b0.x;
    o.y = dc * acc.y + b0.y;
    o.z = dc * acc.z + b0.z;
    o.w = dc * acc.w + b0.w;
    ((float4*)out)[(size_t)node * 32 + lane] = o;
}

// ---------------- launch ------------------------------------------------------
extern "C" void kernel_launch(void* const* d_in, const int* in_sizes, int n_in,
                              void* d_out, int out_size)
{
    const float* x  = (const float*)d_in[0];
    const void*  ei = d_in[1];
    const float* W1 = (const float*)d_in[2];
    const float* b1 = (const float*)d_in[3];
    const float* W2 = (const float*)d_in[4];
    const float* b2 = (const float*)d_in[5];
    float* out = (float*)d_out;

    float* h1; cudaGetSymbolAddress((void**)&h1, g_h1);
    float* a1; cudaGetSymbolAddress((void**)&a1, g_a1);
    float* h2; cudaGetSymbolAddress((void**)&h2, g_h2);

    // 1. dtype detect
    detect_kernel<<<1, 256>>>((const unsigned int*)ei);
    // 2. CSR build
    zero_kernel<<<(N_NODES + 255) / 256, 256>>>();
    count_kernel<<<(N_EDGES + 255) / 256, 256>>>(ei);
    scan_kernel<<<1, 1024>>>();
    fill_kernel<<<(N_EDGES + 255) / 256, 256>>>(ei);

    // 3. layer 1: h1 = x @ W1 ; a1 = relu(agg(h1) + b1)
    {
        dim3 grid((N_NODES + BM - 1) / BM, HID_C / BN);
        sgemm_kernel<<<grid, 256>>>(x, W1, h1, N_NODES, HID_C, IN_C);
    }
    agg256_kernel<<<(N_NODES * 32 + 255) / 256, 256>>>(h1, a1, b1);

    // 4. layer 2: h2 = a1 @ W2 ; out = agg(h2) + b2
    {
        dim3 grid((N_NODES + BM - 1) / BM, OUT_C / BN);
        sgemm_kernel<<<grid, 256>>>(a1, W2, h2, N_NODES, OUT_C, HID_C);
    }
    agg128_kernel<<<(N_NODES * 32 + 255) / 256, 256>>>(h2, out, b2);
}

// round 3
// speedup vs baseline: 1.9962x; 1.9962x over previous
#include <cuda_runtime.h>
#include <cstdint>

#define N_NODES 50000
#define N_EDGES 800000
#define IN_C 256
#define HID_C 256
#define OUT_C 128
#define NB_SCAN ((N_NODES + 255) / 256)

// ---------------- scratch (static device globals; no runtime alloc) ----------
__device__ float g_h1[N_NODES * HID_C];
__device__ float g_a1[N_NODES * HID_C];
__device__ float g_h2[N_NODES * OUT_C];
__device__ int   g_csr[N_EDGES];
__device__ int   g_ptr[N_NODES + 1];
__device__ int   g_cnt[N_NODES];
__device__ int   g_cur[N_NODES];
__device__ float g_dinv[N_NODES];
__device__ int   g_bsum[256];
__device__ int   g_boff[256];
__device__ int   g_is64;

// ---------------- edge_index dtype detection ---------------------------------
__global__ void detect_kernel(const unsigned int* __restrict__ w) {
    __shared__ int nz;
    if (threadIdx.x == 0) nz = 0;
    __syncthreads();
    int bad = 0;
    for (int i = threadIdx.x; i < 4096; i += blockDim.x)
        if (w[2 * i + 1] != 0u) bad = 1;
    if (bad) atomicOr(&nz, 1);
    __syncthreads();
    if (threadIdx.x == 0) g_is64 = (nz == 0) ? 1 : 0;
}

__device__ __forceinline__ int edge_at(const void* ei, long long idx) {
    if (g_is64) return (int)((const long long*)ei)[idx];
    return ((const int*)ei)[idx];
}

// ---------------- CSR build --------------------------------------------------
__global__ void zero_kernel() {
    int i = blockIdx.x * blockDim.x + threadIdx.x;
    if (i < N_NODES) { g_cnt[i] = 0; g_cur[i] = 0; }
    if (i == 0) g_ptr[N_NODES] = N_EDGES;
}

__global__ void count_kernel(const void* __restrict__ ei) {
    int e = blockIdx.x * blockDim.x + threadIdx.x;
    if (e >= N_EDGES) return;
    int c = edge_at(ei, (long long)N_EDGES + e);
    atomicAdd(&g_cnt[c], 1);
}

// parallel exclusive scan: per-block sums -> scan of sums -> per-block scatter
__global__ void scan1_kernel() {
    int i = blockIdx.x * 256 + threadIdx.x;
    int v = (i < N_NODES) ? g_cnt[i] : 0;
    int lane = threadIdx.x & 31, w = threadIdx.x >> 5;
    for (int o = 16; o; o >>= 1) v += __shfl_down_sync(~0u, v, o);
    __shared__ int ws[8];
    if (!lane) ws[w] = v;
    __syncthreads();
    if (threadIdx.x == 0) {
        int s = 0;
        for (int k = 0; k < 8; k++) s += ws[k];
        g_bsum[blockIdx.x] = s;
    }
}

__global__ void scan2_kernel() {
    int t = threadIdx.x;
    int v = (t < NB_SCAN) ? g_bsum[t] : 0;
    int lane = t & 31, w = t >> 5;
    int x = v;
    for (int o = 1; o < 32; o <<= 1) {
        int y = __shfl_up_sync(~0u, x, o);
        if (lane >= o) x += y;
    }
    __shared__ int ws[8], wo[8];
    if (lane == 31) ws[w] = x;
    __syncthreads();
    if (t == 0) {
        int r = 0;
        for (int k = 0; k < 8; k++) { wo[k] = r; r += ws[k]; }
    }
    __syncthreads();
    if (t < NB_SCAN) g_boff[t] = wo[w] + x - v;
}

__global__ void scan3_kernel() {
    int i = blockIdx.x * 256 + threadIdx.x;
    int c = (i < N_NODES) ? g_cnt[i] : 0;
    int lane = threadIdx.x & 31, w = threadIdx.x >> 5;
    int x = c;
    for (int o = 1; o < 32; o <<= 1) {
        int y = __shfl_up_sync(~0u, x, o);
        if (lane >= o) x += y;
    }
    __shared__ int ws[8], wo[8];
    if (lane == 31) ws[w] = x;
    __syncthreads();
    if (threadIdx.x == 0) {
        int r = 0;
        for (int k = 0; k < 8; k++) { wo[k] = r; r += ws[k]; }
    }
    __syncthreads();
    if (i < N_NODES) {
        g_ptr[i] = g_boff[blockIdx.x] + wo[w] + x - c;
        g_dinv[i] = rsqrtf((float)(c + 1));
    }
}

__global__ void fill_kernel(const void* __restrict__ ei) {
    int e = blockIdx.x * blockDim.x + threadIdx.x;
    if (e >= N_EDGES) return;
    int r = edge_at(ei, e);
    int c = edge_at(ei, (long long)N_EDGES + e);
    int pos = g_ptr[c] + atomicAdd(&g_cur[c], 1);
    g_csr[pos] = r;
}

// ---------------- TF32 mma.sync SGEMM: C[M,N] = A[M,K] @ B[K,N] ---------------
// 256 threads = 8 warps in 4(M) x 2(N); each warp owns 32x32 of a 128x64 tile.
// m16n8k8 tf32 fragments; cvt.rna.tf32 applied at SMEM store time.
#define BM 128
#define BN 64
#define BK 32

__device__ __forceinline__ uint32_t tf32_of(float x) {
    uint32_t r;
    asm("cvt.rna.tf32.f32 %0, %1;" : "=r"(r) : "f"(x));
    return r;
}

__device__ __forceinline__ void mma_tf32(float* c, const uint32_t* a, const uint32_t* b) {
    asm volatile(
        "mma.sync.aligned.m16n8k8.row.col.f32.tf32.tf32.f32 "
        "{%0,%1,%2,%3}, {%4,%5,%6,%7}, {%8,%9}, {%0,%1,%2,%3};"
        : "+f"(c[0]), "+f"(c[1]), "+f"(c[2]), "+f"(c[3])
        : "r"(a[0]), "r"(a[1]), "r"(a[2]), "r"(a[3]), "r"(b[0]), "r"(b[1]));
}

__global__ __launch_bounds__(256) void mma_sgemm_kernel(
    const float* __restrict__ A, const float* __restrict__ B,
    float* __restrict__ C, int M, int N, int K)
{
    __shared__ __align__(16) uint32_t As[BM][BK + 4];   // 128 x 36 (pad: 4r+tq banks)
    __shared__ __align__(16) uint32_t Bs[BK][BN + 8];   // 32 x 72  (pad: 8tq+g banks)

    int tid = threadIdx.x;
    int lane = tid & 31, wid = tid >> 5;
    int wm = (wid & 3) * 32;    // warp M offset within tile
    int wn = (wid >> 2) * 32;   // warp N offset within tile
    int m0 = blockIdx.x * BM, n0 = blockIdx.y * BN;
    int g = lane >> 2, tq = lane & 3;

    float acc[2][4][4];
#pragma unroll
    for (int mt = 0; mt < 2; mt++)
#pragma unroll
        for (int nt = 0; nt < 4; nt++)
#pragma unroll
            for (int j = 0; j < 4; j++) acc[mt][nt][j] = 0.0f;

    for (int k0 = 0; k0 < K; k0 += BK) {
        // A tile: 128 rows x 8 float4 slots = 1024, 4 per thread
#pragma unroll
        for (int i = 0; i < 4; i++) {
            int slot = tid + 256 * i;
            int m = slot >> 3, c4 = slot & 7;
            float4 v = make_float4(0.f, 0.f, 0.f, 0.f);
            if (m0 + m < M) v = *(const float4*)(A + (size_t)(m0 + m) * K + k0 + c4 * 4);
            uint4 u = make_uint4(tf32_of(v.x), tf32_of(v.y), tf32_of(v.z), tf32_of(v.w));
            *(uint4*)&As[m][c4 * 4] = u;
        }
        // B tile: 32 rows x 16 float4 slots = 512, 2 per thread
#pragma unroll
        for (int i = 0; i < 2; i++) {
            int slot = tid + 256 * i;
            int r = slot >> 4, c4 = slot & 15;
            float4 v = *(const float4*)(B + (size_t)(k0 + r) * N + n0 + c4 * 4);
            uint4 u = make_uint4(tf32_of(v.x), tf32_of(v.y), tf32_of(v.z), tf32_of(v.w));
            *(uint4*)&Bs[r][c4 * 4] = u;
        }
        __syncthreads();

#pragma unroll
        for (int kk = 0; kk < BK; kk += 8) {
            uint32_t a[2][4], b[4][2];
#pragma unroll
            for (int mt = 0; mt < 2; mt++) {
                int r = wm + mt * 16 + g;
                a[mt][0] = As[r][kk + tq];
                a[mt][1] = As[r + 8][kk + tq];
                a[mt][2] = As[r][kk + tq + 4];
                a[mt][3] = As[r + 8][kk + tq + 4];
            }
#pragma unroll
            for (int nt = 0; nt < 4; nt++) {
                int n = wn + nt * 8 + g;
                b[nt][0] = Bs[kk + tq][n];
                b[nt][1] = Bs[kk + tq + 4][n];
            }
#pragma unroll
            for (int mt = 0; mt < 2; mt++)
#pragma unroll
                for (int nt = 0; nt < 4; nt++)
                    mma_tf32(acc[mt][nt], a[mt], b[nt]);
        }
        __syncthreads();
    }

    // writeback: c0,c1 -> (row, 2tq), (row, 2tq+1); c2,c3 -> row+8
#pragma unroll
    for (int mt = 0; mt < 2; mt++) {
        int row = m0 + wm + mt * 16 + g;
#pragma unroll
        for (int nt = 0; nt < 4; nt++) {
            int col = n0 + wn + nt * 8 + tq * 2;
            if (row < M)
                *(float2*)(C + (size_t)row * N + col) =
                    make_float2(acc[mt][nt][0], acc[mt][nt][1]);
            if (row + 8 < M)
                *(float2*)(C + (size_t)(row + 8) * N + col) =
                    make_float2(acc[mt][nt][2], acc[mt][nt][3]);
        }
    }
}

// ---------------- aggregation ------------------------------------------------
__device__ __forceinline__ float4 f4_fma(float w, float4 v, float4 a) {
    a.x += w * v.x; a.y += w * v.y; a.z += w * v.z; a.w += w * v.w; return a;
}

__global__ __launch_bounds__(256) void agg256_kernel(
    const float* __restrict__ h, float* __restrict__ out,
    const float* __restrict__ bias)
{
    int warp = (blockIdx.x * blockDim.x + threadIdx.x) >> 5;
    int lane = threadIdx.x & 31;
    if (warp >= N_NODES) return;
    int node = warp;

    const float4* hv = (const float4*)h;
    int p0 = g_ptr[node], p1 = g_ptr[node + 1];
    float dc = g_dinv[node];

    const float4* selfr = hv + (size_t)node * 64;
    float4 acc0 = f4_fma(dc, selfr[lane],      make_float4(0.f, 0.f, 0.f, 0.f));
    float4 acc1 = f4_fma(dc, selfr[lane + 32], make_float4(0.f, 0.f, 0.f, 0.f));

    int e = p0;
    for (; e + 2 <= p1; e += 2) {
        int s0 = g_csr[e], s1 = g_csr[e + 1];
        float w0 = g_dinv[s0], w1 = g_dinv[s1];
        const float4* r0 = hv + (size_t)s0 * 64;
        const float4* r1 = hv + (size_t)s1 * 64;
        acc0 = f4_fma(w0, r0[lane], acc0);
        acc1 = f4_fma(w0, r0[lane + 32], acc1);
        acc0 = f4_fma(w1, r1[lane], acc0);
        acc1 = f4_fma(w1, r1[lane + 32], acc1);
    }
    if (e < p1) {
        int s0 = g_csr[e];
        float w0 = g_dinv[s0];
        const float4* r0 = hv + (size_t)s0 * 64;
        acc0 = f4_fma(w0, r0[lane], acc0);
        acc1 = f4_fma(w0, r0[lane + 32], acc1);
    }

    float4 b0 = ((const float4*)bias)[lane];
    float4 b1v = ((const float4*)bias)[lane + 32];
    float4 o0, o1;
    o0.x = fmaxf(dc * acc0.x + b0.x, 0.f);
    o0.y = fmaxf(dc * acc0.y + b0.y, 0.f);
    o0.z = fmaxf(dc * acc0.z + b0.z, 0.f);
    o0.w = fmaxf(dc * acc0.w + b0.w, 0.f);
    o1.x = fmaxf(dc * acc1.x + b1v.x, 0.f);
    o1.y = fmaxf(dc * acc1.y + b1v.y, 0.f);
    o1.z = fmaxf(dc * acc1.z + b1v.z, 0.f);
    o1.w = fmaxf(dc * acc1.w + b1v.w, 0.f);

    float4* ov = (float4*)out + (size_t)node * 64;
    ov[lane] = o0;
    ov[lane + 32] = o1;
}

__global__ __launch_bounds__(256) void agg128_kernel(
    const float* __restrict__ h, float* __restrict__ out,
    const float* __restrict__ bias)
{
    int warp = (blockIdx.x * blockDim.x + threadIdx.x) >> 5;
    int lane = threadIdx.x & 31;
    if (warp >= N_NODES) return;
    int node = warp;

    const float4* hv = (const float4*)h;
    int p0 = g_ptr[node], p1 = g_ptr[node + 1];
    float dc = g_dinv[node];

    const float4* selfr = hv + (size_t)node * 32;
    float4 acc = f4_fma(dc, selfr[lane], make_float4(0.f, 0.f, 0.f, 0.f));

    int e = p0;
    for (; e + 2 <= p1; e += 2) {
        int s0 = g_csr[e], s1 = g_csr[e + 1];
        float w0 = g_dinv[s0], w1 = g_dinv[s1];
        acc = f4_fma(w0, (hv + (size_t)s0 * 32)[lane], acc);
        acc = f4_fma(w1, (hv + (size_t)s1 * 32)[lane], acc);
    }
    if (e < p1) {
        int s0 = g_csr[e];
        acc = f4_fma(g_dinv[s0], (hv + (size_t)s0 * 32)[lane], acc);
    }

    float4 b0 = ((const float4*)bias)[lane];
    float4 o;
    o.x = dc * acc.x + b0.x;
    o.y = dc * acc.y + b0.y;
    o.z = dc * acc.z + b0.z;
    o.w = dc * acc.w + b0.w;
    ((float4*)out)[(size_t)node * 32 + lane] = o;
}

// ---------------- launch ------------------------------------------------------
extern "C" void kernel_launch(void* const* d_in, const int* in_sizes, int n_in,
                              void* d_out, int out_size)
{
    const float* x  = (const float*)d_in[0];
    const void*  ei = d_in[1];
    const float* W1 = (const float*)d_in[2];
    const float* b1 = (const float*)d_in[3];
    const float* W2 = (const float*)d_in[4];
    const float* b2 = (const float*)d_in[5];
    float* out = (float*)d_out;

    float* h1; cudaGetSymbolAddress((void**)&h1, g_h1);
    float* a1; cudaGetSymbolAddress((void**)&a1, g_a1);
    float* h2; cudaGetSymbolAddress((void**)&h2, g_h2);

    // dtype detect + CSR build
    detect_kernel<<<1, 256>>>((const unsigned int*)ei);
    zero_kernel<<<(N_NODES + 255) / 256, 256>>>();
    count_kernel<<<(N_EDGES + 255) / 256, 256>>>(ei);
    scan1_kernel<<<NB_SCAN, 256>>>();
    scan2_kernel<<<1, 256>>>();
    scan3_kernel<<<NB_SCAN, 256>>>();
    fill_kernel<<<(N_EDGES + 255) / 256, 256>>>(ei);

    int grid_m = (N_NODES + BM - 1) / BM;   // 391
    // layer 1: h1 = x @ W1 ; a1 = relu(agg(h1) + b1)
    mma_sgemm_kernel<<<dim3(grid_m, HID_C / BN), 256>>>(x, W1, h1, N_NODES, HID_C, IN_C);
    agg256_kernel<<<(N_NODES * 32 + 255) / 256, 256>>>(h1, a1, b1);
    // layer 2: h2 = a1 @ W2 ; out = agg(h2) + b2
    mma_sgemm_kernel<<<dim3(grid_m, OUT_C / BN), 256>>>(a1, W2, h2, N_NODES, OUT_C, HID_C);
    agg128_kernel<<<(N_NODES * 32 + 255) / 256, 256>>>(h2, out, b2);
}

// round 4
// speedup vs baseline: 2.2206x; 1.1124x over previous
#include <cuda_runtime.h>
#include <cuda_fp16.h>
#include <cstdint>

#define N_NODES 50000
#define N_EDGES 800000
#define IN_C 256
#define HID_C 256
#define OUT_C 128
#define NB_SCAN ((N_NODES + 255) / 256)

// ---------------- scratch (static device globals; no runtime alloc) ----------
__device__ __align__(256) __half g_h1[N_NODES * HID_C];
__device__ __align__(256) __half g_a1[N_NODES * HID_C];
__device__ __align__(256) __half g_h2[N_NODES * OUT_C];
__device__ int   g_csr[N_EDGES];
__device__ int   g_ptr[N_NODES + 1];
__device__ int   g_cnt[N_NODES];
__device__ int   g_cur[N_NODES];
__device__ float g_dinv[N_NODES];
__device__ int   g_bsum[256];
__device__ int   g_boff[256];
__device__ int   g_is64;

// ---------------- edge_index dtype detection ---------------------------------
__global__ void detect_kernel(const unsigned int* __restrict__ w) {
    __shared__ int nz;
    if (threadIdx.x == 0) nz = 0;
    __syncthreads();
    int bad = 0;
    for (int i = threadIdx.x; i < 4096; i += blockDim.x)
        if (w[2 * i + 1] != 0u) bad = 1;
    if (bad) atomicOr(&nz, 1);
    __syncthreads();
    if (threadIdx.x == 0) g_is64 = (nz == 0) ? 1 : 0;
}

__device__ __forceinline__ int edge_at(const void* ei, long long idx) {
    if (g_is64) return (int)((const long long*)ei)[idx];
    return ((const int*)ei)[idx];
}

// ---------------- CSR build --------------------------------------------------
__global__ void zero_kernel() {
    int i = blockIdx.x * blockDim.x + threadIdx.x;
    if (i < N_NODES) { g_cnt[i] = 0; g_cur[i] = 0; }
    if (i == 0) g_ptr[N_NODES] = N_EDGES;
}

__global__ void count_kernel(const void* __restrict__ ei) {
    int e = blockIdx.x * blockDim.x + threadIdx.x;
    if (e >= N_EDGES) return;
    int c = edge_at(ei, (long long)N_EDGES + e);
    atomicAdd(&g_cnt[c], 1);
}

__global__ void scan1_kernel() {
    int i = blockIdx.x * 256 + threadIdx.x;
    int v = (i < N_NODES) ? g_cnt[i] : 0;
    int lane = threadIdx.x & 31, w = threadIdx.x >> 5;
    for (int o = 16; o; o >>= 1) v += __shfl_down_sync(~0u, v, o);
    __shared__ int ws[8];
    if (!lane) ws[w] = v;
    __syncthreads();
    if (threadIdx.x == 0) {
        int s = 0;
        for (int k = 0; k < 8; k++) s += ws[k];
        g_bsum[blockIdx.x] = s;
    }
}

__global__ void scan2_kernel() {
    int t = threadIdx.x;
    int v = (t < NB_SCAN) ? g_bsum[t] : 0;
    int lane = t & 31, w = t >> 5;
    int x = v;
    for (int o = 1; o < 32; o <<= 1) {
        int y = __shfl_up_sync(~0u, x, o);
        if (lane >= o) x += y;
    }
    __shared__ int ws[8], wo[8];
    if (lane == 31) ws[w] = x;
    __syncthreads();
    if (t == 0) {
        int r = 0;
        for (int k = 0; k < 8; k++) { wo[k] = r; r += ws[k]; }
    }
    __syncthreads();
    if (t < NB_SCAN) g_boff[t] = wo[w] + x - v;
}

__global__ void scan3_kernel() {
    int i = blockIdx.x * 256 + threadIdx.x;
    int c = (i < N_NODES) ? g_cnt[i] : 0;
    int lane = threadIdx.x & 31, w = threadIdx.x >> 5;
    int x = c;
    for (int o = 1; o < 32; o <<= 1) {
        int y = __shfl_up_sync(~0u, x, o);
        if (lane >= o) x += y;
    }
    __shared__ int ws[8], wo[8];
    if (lane == 31) ws[w] = x;
    __syncthreads();
    if (threadIdx.x == 0) {
        int r = 0;
        for (int k = 0; k < 8; k++) { wo[k] = r; r += ws[k]; }
    }
    __syncthreads();
    if (i < N_NODES) {
        g_ptr[i] = g_boff[blockIdx.x] + wo[w] + x - c;
        g_dinv[i] = rsqrtf((float)(c + 1));
    }
}

__global__ void fill_kernel(const void* __restrict__ ei) {
    int e = blockIdx.x * blockDim.x + threadIdx.x;
    if (e >= N_EDGES) return;
    int r = edge_at(ei, e);
    int c = edge_at(ei, (long long)N_EDGES + e);
    int pos = g_ptr[c] + atomicAdd(&g_cur[c], 1);
    g_csr[pos] = r;
}

// ---------------- TF32 mma.sync SGEMM: C[M,N] = A[M,K] @ B[K,N] ---------------
// 256 threads = 8 warps (4M x 2N); each warp owns 32x32 of a 128x64 tile.
// A dtype: float or __half; C dtype: float or __half. fp32 accumulate.
#define BM 128
#define BN 64
#define BK 32

__device__ __forceinline__ uint32_t tf32_of(float x) {
    uint32_t r;
    asm("cvt.rna.tf32.f32 %0, %1;" : "=r"(r) : "f"(x));
    return r;
}

__device__ __forceinline__ void mma_tf32(float* c, const uint32_t* a, const uint32_t* b) {
    asm volatile(
        "mma.sync.aligned.m16n8k8.row.col.f32.tf32.tf32.f32 "
        "{%0,%1,%2,%3}, {%4,%5,%6,%7}, {%8,%9}, {%0,%1,%2,%3};"
        : "+f"(c[0]), "+f"(c[1]), "+f"(c[2]), "+f"(c[3])
        : "r"(a[0]), "r"(a[1]), "r"(a[2]), "r"(a[3]), "r"(b[0]), "r"(b[1]));
}

template <typename TA, typename TC>
__global__ __launch_bounds__(256) void mma_sgemm_kernel(
    const TA* __restrict__ A, const float* __restrict__ B,
    TC* __restrict__ C, int M, int N, int K)
{
    __shared__ __align__(16) uint32_t As[BM][BK + 4];
    __shared__ __align__(16) uint32_t Bs[BK][BN + 8];

    int tid = threadIdx.x;
    int lane = tid & 31, wid = tid >> 5;
    int wm = (wid & 3) * 32;
    int wn = (wid >> 2) * 32;
    int m0 = blockIdx.x * BM, n0 = blockIdx.y * BN;
    int g = lane >> 2, tq = lane & 3;

    float acc[2][4][4];
#pragma unroll
    for (int mt = 0; mt < 2; mt++)
#pragma unroll
        for (int nt = 0; nt < 4; nt++)
#pragma unroll
            for (int j = 0; j < 4; j++) acc[mt][nt][j] = 0.0f;

    for (int k0 = 0; k0 < K; k0 += BK) {
        if constexpr (sizeof(TA) == 4) {
            // fp32 A: 1024 float4 slots, 4 per thread
#pragma unroll
            for (int i = 0; i < 4; i++) {
                int slot = tid + 256 * i;
                int m = slot >> 3, c4 = slot & 7;
                float4 v = make_float4(0.f, 0.f, 0.f, 0.f);
                if (m0 + m < M)
                    v = *(const float4*)((const float*)A + (size_t)(m0 + m) * K + k0 + c4 * 4);
                uint4 u = make_uint4(tf32_of(v.x), tf32_of(v.y), tf32_of(v.z), tf32_of(v.w));
                *(uint4*)&As[m][c4 * 4] = u;
            }
        } else {
            // fp16 A: 512 uint4 slots (8 halves each), 2 per thread
#pragma unroll
            for (int i = 0; i < 2; i++) {
                int slot = tid + 256 * i;
                int m = slot >> 2, c8 = slot & 3;
                uint4 raw = make_uint4(0u, 0u, 0u, 0u);
                if (m0 + m < M)
                    raw = ((const uint4*)((const __half*)A + (size_t)(m0 + m) * K + k0))[c8];
                const __half2* hp = (const __half2*)&raw;
                uint32_t w[8];
#pragma unroll
                for (int j = 0; j < 4; j++) {
                    float2 f = __half22float2(hp[j]);
                    w[2 * j] = tf32_of(f.x);
                    w[2 * j + 1] = tf32_of(f.y);
                }
                *(uint4*)&As[m][c8 * 8]     = make_uint4(w[0], w[1], w[2], w[3]);
                *(uint4*)&As[m][c8 * 8 + 4] = make_uint4(w[4], w[5], w[6], w[7]);
            }
        }
        // B tile (fp32 weights): 512 float4 slots, 2 per thread
#pragma unroll
        for (int i = 0; i < 2; i++) {
            int slot = tid + 256 * i;
            int r = slot >> 4, c4 = slot & 15;
            float4 v = *(const float4*)(B + (size_t)(k0 + r) * N + n0 + c4 * 4);
            uint4 u = make_uint4(tf32_of(v.x), tf32_of(v.y), tf32_of(v.z), tf32_of(v.w));
            *(uint4*)&Bs[r][c4 * 4] = u;
        }
        __syncthreads();

#pragma unroll
        for (int kk = 0; kk < BK; kk += 8) {
            uint32_t a[2][4], b[4][2];
#pragma unroll
            for (int mt = 0; mt < 2; mt++) {
                int r = wm + mt * 16 + g;
                a[mt][0] = As[r][kk + tq];
                a[mt][1] = As[r + 8][kk + tq];
                a[mt][2] = As[r][kk + tq + 4];
                a[mt][3] = As[r + 8][kk + tq + 4];
            }
#pragma unroll
            for (int nt = 0; nt < 4; nt++) {
                int n = wn + nt * 8 + g;
                b[nt][0] = Bs[kk + tq][n];
                b[nt][1] = Bs[kk + tq + 4][n];
            }
#pragma unroll
            for (int mt = 0; mt < 2; mt++)
#pragma unroll
                for (int nt = 0; nt < 4; nt++)
                    mma_tf32(acc[mt][nt], a[mt], b[nt]);
        }
        __syncthreads();
    }

#pragma unroll
    for (int mt = 0; mt < 2; mt++) {
        int row = m0 + wm + mt * 16 + g;
#pragma unroll
        for (int nt = 0; nt < 4; nt++) {
            int col = n0 + wn + nt * 8 + tq * 2;
            if constexpr (sizeof(TC) == 4) {
                if (row < M)
                    *(float2*)((float*)C + (size_t)row * N + col) =
                        make_float2(acc[mt][nt][0], acc[mt][nt][1]);
                if (row + 8 < M)
                    *(float2*)((float*)C + (size_t)(row + 8) * N + col) =
                        make_float2(acc[mt][nt][2], acc[mt][nt][3]);
            } else {
                if (row < M)
                    *(__half2*)((__half*)C + (size_t)row * N + col) =
                        __floats2half2_rn(acc[mt][nt][0], acc[mt][nt][1]);
                if (row + 8 < M)
                    *(__half2*)((__half*)C + (size_t)(row + 8) * N + col) =
                        __floats2half2_rn(acc[mt][nt][2], acc[mt][nt][3]);
            }
        }
    }
}

// ---------------- aggregation (fp16 features, fp32 accumulate) ---------------
__device__ __forceinline__ void h8_fma(float w, uint4 v, float* acc) {
    const __half2* hp = (const __half2*)&v;
#pragma unroll
    for (int i = 0; i < 4; i++) {
        float2 f = __half22float2(hp[i]);
        acc[2 * i]     += w * f.x;
        acc[2 * i + 1] += w * f.y;
    }
}

__device__ __forceinline__ void h4_fma(float w, uint2 v, float* acc) {
    const __half2* hp = (const __half2*)&v;
#pragma unroll
    for (int i = 0; i < 2; i++) {
        float2 f = __half22float2(hp[i]);
        acc[2 * i]     += w * f.x;
        acc[2 * i + 1] += w * f.y;
    }
}

// 256 channels: warp per node, lane owns 8 channels (one uint4 of halves)
__global__ __launch_bounds__(256) void agg256_kernel(
    const __half* __restrict__ h, __half* __restrict__ out,
    const float* __restrict__ bias)
{
    int warp = (blockIdx.x * blockDim.x + threadIdx.x) >> 5;
    int lane = threadIdx.x & 31;
    if (warp >= N_NODES) return;
    int node = warp;

    const uint4* hv = (const uint4*)h;   // 32 uint4 per row
    int p0 = g_ptr[node], p1 = g_ptr[node + 1];
    float dc = g_dinv[node];

    float acc[8];
#pragma unroll
    for (int j = 0; j < 8; j++) acc[j] = 0.0f;
    h8_fma(dc, hv[(size_t)node * 32 + lane], acc);

    int e = p0;
    for (; e + 2 <= p1; e += 2) {
        int s0 = g_csr[e], s1 = g_csr[e + 1];
        float w0 = g_dinv[s0], w1 = g_dinv[s1];
        uint4 v0 = hv[(size_t)s0 * 32 + lane];
        uint4 v1 = hv[(size_t)s1 * 32 + lane];
        h8_fma(w0, v0, acc);
        h8_fma(w1, v1, acc);
    }
    if (e < p1) {
        int s0 = g_csr[e];
        h8_fma(g_dinv[s0], hv[(size_t)s0 * 32 + lane], acc);
    }

    float4 b0 = ((const float4*)bias)[lane * 2];
    float4 b1 = ((const float4*)bias)[lane * 2 + 1];
    float r[8];
    r[0] = fmaxf(dc * acc[0] + b0.x, 0.f);
    r[1] = fmaxf(dc * acc[1] + b0.y, 0.f);
    r[2] = fmaxf(dc * acc[2] + b0.z, 0.f);
    r[3] = fmaxf(dc * acc[3] + b0.w, 0.f);
    r[4] = fmaxf(dc * acc[4] + b1.x, 0.f);
    r[5] = fmaxf(dc * acc[5] + b1.y, 0.f);
    r[6] = fmaxf(dc * acc[6] + b1.z, 0.f);
    r[7] = fmaxf(dc * acc[7] + b1.w, 0.f);

    uint4 o;
    __half2* op = (__half2*)&o;
    op[0] = __floats2half2_rn(r[0], r[1]);
    op[1] = __floats2half2_rn(r[2], r[3]);
    op[2] = __floats2half2_rn(r[4], r[5]);
    op[3] = __floats2half2_rn(r[6], r[7]);
    ((uint4*)out)[(size_t)node * 32 + lane] = o;
}

// 128 channels: warp per node, lane owns 4 channels; fp32 output (final)
__global__ __launch_bounds__(256) void agg128_kernel(
    const __half* __restrict__ h, float* __restrict__ out,
    const float* __restrict__ bias)
{
    int warp = (blockIdx.x * blockDim.x + threadIdx.x) >> 5;
    int lane = threadIdx.x & 31;
    if (warp >= N_NODES) return;
    int node = warp;

    const uint2* hv = (const uint2*)h;   // 32 uint2 per row
    int p0 = g_ptr[node], p1 = g_ptr[node + 1];
    float dc = g_dinv[node];

    float acc[4];
#pragma unroll
    for (int j = 0; j < 4; j++) acc[j] = 0.0f;
    h4_fma(dc, hv[(size_t)node * 32 + lane], acc);

    int e = p0;
    for (; e + 2 <= p1; e += 2) {
        int s0 = g_csr[e], s1 = g_csr[e + 1];
        float w0 = g_dinv[s0], w1 = g_dinv[s1];
        uint2 v0 = hv[(size_t)s0 * 32 + lane];
        uint2 v1 = hv[(size_t)s1 * 32 + lane];
        h4_fma(w0, v0, acc);
        h4_fma(w1, v1, acc);
    }
    if (e < p1) {
        int s0 = g_csr[e];
        h4_fma(g_dinv[s0], hv[(size_t)s0 * 32 + lane], acc);
    }

    float4 b0 = ((const float4*)bias)[lane];
    float4 o;
    o.x = dc * acc[0] + b0.x;
    o.y = dc * acc[1] + b0.y;
    o.z = dc * acc[2] + b0.z;
    o.w = dc * acc[3] + b0.w;
    ((float4*)out)[(size_t)node * 32 + lane] = o;
}

// ---------------- launch ------------------------------------------------------
extern "C" void kernel_launch(void* const* d_in, const int* in_sizes, int n_in,
                              void* d_out, int out_size)
{
    const float* x  = (const float*)d_in[0];
    const void*  ei = d_in[1];
    const float* W1 = (const float*)d_in[2];
    const float* b1 = (const float*)d_in[3];
    const float* W2 = (const float*)d_in[4];
    const float* b2 = (const float*)d_in[5];
    float* out = (float*)d_out;

    __half* h1; cudaGetSymbolAddress((void**)&h1, g_h1);
    __half* a1; cudaGetSymbolAddress((void**)&a1, g_a1);
    __half* h2; cudaGetSymbolAddress((void**)&h2, g_h2);

    // dtype detect + CSR build
    detect_kernel<<<1, 256>>>((const unsigned int*)ei);
    zero_kernel<<<(N_NODES + 255) / 256, 256>>>();
    count_kernel<<<(N_EDGES + 255) / 256, 256>>>(ei);
    scan1_kernel<<<NB_SCAN, 256>>>();
    scan2_kernel<<<1, 256>>>();
    scan3_kernel<<<NB_SCAN, 256>>>();
    fill_kernel<<<(N_EDGES + 255) / 256, 256>>>(ei);

    int grid_m = (N_NODES + BM - 1) / BM;   // 391
    // layer 1: h1 = x @ W1 (fp16 out) ; a1 = relu(agg(h1) + b1) (fp16)
    mma_sgemm_kernel<float, __half>
        <<<dim3(grid_m, HID_C / BN), 256>>>(x, W1, h1, N_NODES, HID_C, IN_C);
    agg256_kernel<<<(N_NODES * 32 + 255) / 256, 256>>>(h1, a1, b1);
    // layer 2: h2 = a1 @ W2 (fp16 out) ; out = agg(h2) + b2 (fp32)
    mma_sgemm_kernel<__half, __half>
        <<<dim3(grid_m, OUT_C / BN), 256>>>(a1, W2, h2, N_NODES, OUT_C, HID_C);
    agg128_kernel<<<(N_NODES * 32 + 255) / 256, 256>>>(h2, out, b2);
}

// round 5
// speedup vs baseline: 2.3653x; 1.0652x over previous
#include <cuda_runtime.h>
#include <cuda_fp16.h>
#include <cstdint>

#define N_NODES 50000
#define N_EDGES 800000
#define IN_C 256
#define HID_C 256
#define OUT_C 128
#define NB_SCAN ((N_NODES + 255) / 256)

// ---------------- scratch (static device globals; no runtime alloc) ----------
__device__ __align__(256) __half g_h1[N_NODES * HID_C];
__device__ __align__(256) __half g_a1[N_NODES * HID_C];
__device__ __align__(256) __half g_h2[N_NODES * OUT_C];
__device__ __align__(256) __half g_W2h[OUT_C * HID_C];   // W2^T fp16 [N=128][K=256]
__device__ int   g_csr[N_EDGES];
__device__ int   g_ptr[N_NODES + 1];
__device__ int   g_cnt[N_NODES];
__device__ int   g_cur[N_NODES];
__device__ float g_dinv[N_NODES];
__device__ int   g_bsum[256];
__device__ int   g_boff[256];
__device__ int   g_is64;

// ---------------- edge_index dtype detection ---------------------------------
__global__ void detect_kernel(const unsigned int* __restrict__ w) {
    __shared__ int nz;
    if (threadIdx.x == 0) nz = 0;
    __syncthreads();
    int bad = 0;
    for (int i = threadIdx.x; i < 4096; i += blockDim.x)
        if (w[2 * i + 1] != 0u) bad = 1;
    if (bad) atomicOr(&nz, 1);
    __syncthreads();
    if (threadIdx.x == 0) g_is64 = (nz == 0) ? 1 : 0;
}

__device__ __forceinline__ int edge_at(const void* ei, long long idx) {
    if (g_is64) return (int)((const long long*)ei)[idx];
    return ((const int*)ei)[idx];
}

// ---------------- CSR build --------------------------------------------------
__global__ void zero_kernel() {
    int i = blockIdx.x * blockDim.x + threadIdx.x;
    if (i < N_NODES) { g_cnt[i] = 0; g_cur[i] = 0; }
    if (i == 0) g_ptr[N_NODES] = N_EDGES;
}

__global__ void count_kernel(const void* __restrict__ ei) {
    int e = blockIdx.x * blockDim.x + threadIdx.x;
    if (e >= N_EDGES) return;
    int c = edge_at(ei, (long long)N_EDGES + e);
    atomicAdd(&g_cnt[c], 1);
}

__global__ void scan1_kernel() {
    int i = blockIdx.x * 256 + threadIdx.x;
    int v = (i < N_NODES) ? g_cnt[i] : 0;
    int lane = threadIdx.x & 31, w = threadIdx.x >> 5;
    for (int o = 16; o; o >>= 1) v += __shfl_down_sync(~0u, v, o);
    __shared__ int ws[8];
    if (!lane) ws[w] = v;
    __syncthreads();
    if (threadIdx.x == 0) {
        int s = 0;
        for (int k = 0; k < 8; k++) s += ws[k];
        g_bsum[blockIdx.x] = s;
    }
}

__global__ void scan2_kernel() {
    int t = threadIdx.x;
    int v = (t < NB_SCAN) ? g_bsum[t] : 0;
    int lane = t & 31, w = t >> 5;
    int x = v;
    for (int o = 1; o < 32; o <<= 1) {
        int y = __shfl_up_sync(~0u, x, o);
        if (lane >= o) x += y;
    }
    __shared__ int ws[8], wo[8];
    if (lane == 31) ws[w] = x;
    __syncthreads();
    if (t == 0) {
        int r = 0;
        for (int k = 0; k < 8; k++) { wo[k] = r; r += ws[k]; }
    }
    __syncthreads();
    if (t < NB_SCAN) g_boff[t] = wo[w] + x - v;
}

__global__ void scan3_kernel() {
    int i = blockIdx.x * 256 + threadIdx.x;
    int c = (i < N_NODES) ? g_cnt[i] : 0;
    int lane = threadIdx.x & 31, w = threadIdx.x >> 5;
    int x = c;
    for (int o = 1; o < 32; o <<= 1) {
        int y = __shfl_up_sync(~0u, x, o);
        if (lane >= o) x += y;
    }
    __shared__ int ws[8], wo[8];
    if (lane == 31) ws[w] = x;
    __syncthreads();
    if (threadIdx.x == 0) {
        int r = 0;
        for (int k = 0; k < 8; k++) { wo[k] = r; r += ws[k]; }
    }
    __syncthreads();
    if (i < N_NODES) {
        g_ptr[i] = g_boff[blockIdx.x] + wo[w] + x - c;
        g_dinv[i] = rsqrtf((float)(c + 1));
    }
}

__global__ void fill_kernel(const void* __restrict__ ei) {
    int e = blockIdx.x * blockDim.x + threadIdx.x;
    if (e >= N_EDGES) return;
    int r = edge_at(ei, e);
    int c = edge_at(ei, (long long)N_EDGES + e);
    int pos = g_ptr[c] + atomicAdd(&g_cur[c], 1);
    g_csr[pos] = r;
}

// ---------------- W2 transpose+convert: W2h[n][k] = fp16(W2[k][n]) ------------
__global__ void transpose_h_kernel(const float* __restrict__ W, __half* __restrict__ WT,
                                   int Kd, int Nd) {
    __shared__ float t[32][33];
    int bx = blockIdx.x * 32, by = blockIdx.y * 32;
    int x = threadIdx.x, y = threadIdx.y;
#pragma unroll
    for (int j = 0; j < 32; j += 8)
        t[y + j][x] = W[(size_t)(by + y + j) * Nd + bx + x];
    __syncthreads();
#pragma unroll
    for (int j = 0; j < 32; j += 8)
        WT[(size_t)(bx + y + j) * Kd + by + x] = __float2half(t[x][y + j]);
}

// ---------------- GEMM tiling constants ---------------------------------------
#define BM 128
#define BN 64
#define BK 32

// ---------------- TF32 mma.sync GEMM1: C[M,N] = A[M,K] @ B[K,N], fp16 out -----
__device__ __forceinline__ uint32_t tf32_of(float x) {
    uint32_t r;
    asm("cvt.rna.tf32.f32 %0, %1;" : "=r"(r) : "f"(x));
    return r;
}

__device__ __forceinline__ void mma_tf32(float* c, const uint32_t* a, const uint32_t* b) {
    asm volatile(
        "mma.sync.aligned.m16n8k8.row.col.f32.tf32.tf32.f32 "
        "{%0,%1,%2,%3}, {%4,%5,%6,%7}, {%8,%9}, {%0,%1,%2,%3};"
        : "+f"(c[0]), "+f"(c[1]), "+f"(c[2]), "+f"(c[3])
        : "r"(a[0]), "r"(a[1]), "r"(a[2]), "r"(a[3]), "r"(b[0]), "r"(b[1]));
}

__global__ __launch_bounds__(256) void mma_sgemm_kernel(
    const float* __restrict__ A, const float* __restrict__ B,
    __half* __restrict__ C, int M, int N, int K)
{
    __shared__ __align__(16) uint32_t As[BM][BK + 4];
    __shared__ __align__(16) uint32_t Bs[BK][BN + 8];

    int tid = threadIdx.x;
    int lane = tid & 31, wid = tid >> 5;
    int wm = (wid & 3) * 32;
    int wn = (wid >> 2) * 32;
    int m0 = blockIdx.x * BM, n0 = blockIdx.y * BN;
    int g = lane >> 2, tq = lane & 3;

    float acc[2][4][4];
#pragma unroll
    for (int mt = 0; mt < 2; mt++)
#pragma unroll
        for (int nt = 0; nt < 4; nt++)
#pragma unroll
            for (int j = 0; j < 4; j++) acc[mt][nt][j] = 0.0f;

    for (int k0 = 0; k0 < K; k0 += BK) {
#pragma unroll
        for (int i = 0; i < 4; i++) {
            int slot = tid + 256 * i;
            int m = slot >> 3, c4 = slot & 7;
            float4 v = make_float4(0.f, 0.f, 0.f, 0.f);
            if (m0 + m < M)
                v = *(const float4*)(A + (size_t)(m0 + m) * K + k0 + c4 * 4);
            uint4 u = make_uint4(tf32_of(v.x), tf32_of(v.y), tf32_of(v.z), tf32_of(v.w));
            *(uint4*)&As[m][c4 * 4] = u;
        }
#pragma unroll
        for (int i = 0; i < 2; i++) {
            int slot = tid + 256 * i;
            int r = slot >> 4, c4 = slot & 15;
            float4 v = *(const float4*)(B + (size_t)(k0 + r) * N + n0 + c4 * 4);
            uint4 u = make_uint4(tf32_of(v.x), tf32_of(v.y), tf32_of(v.z), tf32_of(v.w));
            *(uint4*)&Bs[r][c4 * 4] = u;
        }
        __syncthreads();

#pragma unroll
        for (int kk = 0; kk < BK; kk += 8) {
            uint32_t a[2][4], b[4][2];
#pragma unroll
            for (int mt = 0; mt < 2; mt++) {
                int r = wm + mt * 16 + g;
                a[mt][0] = As[r][kk + tq];
                a[mt][1] = As[r + 8][kk + tq];
                a[mt][2] = As[r][kk + tq + 4];
                a[mt][3] = As[r + 8][kk + tq + 4];
            }
#pragma unroll
            for (int nt = 0; nt < 4; nt++) {
                int n = wn + nt * 8 + g;
                b[nt][0] = Bs[kk + tq][n];
                b[nt][1] = Bs[kk + tq + 4][n];
            }
#pragma unroll
            for (int mt = 0; mt < 2; mt++)
#pragma unroll
                for (int nt = 0; nt < 4; nt++)
                    mma_tf32(acc[mt][nt], a[mt], b[nt]);
        }
        __syncthreads();
    }

#pragma unroll
    for (int mt = 0; mt < 2; mt++) {
        int row = m0 + wm + mt * 16 + g;
#pragma unroll
        for (int nt = 0; nt < 4; nt++) {
            int col = n0 + wn + nt * 8 + tq * 2;
            if (row < M)
                *(__half2*)(C + (size_t)row * N + col) =
                    __floats2half2_rn(acc[mt][nt][0], acc[mt][nt][1]);
            if (row + 8 < M)
                *(__half2*)(C + (size_t)(row + 8) * N + col) =
                    __floats2half2_rn(acc[mt][nt][2], acc[mt][nt][3]);
        }
    }
}

// ---------------- FP16 mma.sync GEMM2: C[M,N] = A[M,K] @ Bt[N,K]^T ------------
// A fp16 row-major, Bt fp16 [N][K] (pre-transposed), fp32 accumulate, fp16 out.
__device__ __forceinline__ void mma_f16(float* c, const uint32_t* a, const uint32_t* b) {
    asm volatile(
        "mma.sync.aligned.m16n8k16.row.col.f32.f16.f16.f32 "
        "{%0,%1,%2,%3}, {%4,%5,%6,%7}, {%8,%9}, {%0,%1,%2,%3};"
        : "+f"(c[0]), "+f"(c[1]), "+f"(c[2]), "+f"(c[3])
        : "r"(a[0]), "r"(a[1]), "r"(a[2]), "r"(a[3]), "r"(b[0]), "r"(b[1]));
}

__global__ __launch_bounds__(256) void mma_hgemm_kernel(
    const __half* __restrict__ A, const __half* __restrict__ Bt,
    __half* __restrict__ C, int M, int N, int K)
{
    __shared__ __align__(16) __half As[BM][BK + 8];   // 128 x 40 halves (80B rows)
    __shared__ __align__(16) __half Bs[BN][BK + 8];   // 64 x 40 halves

    int tid = threadIdx.x;
    int lane = tid & 31, wid = tid >> 5;
    int wm = (wid & 3) * 32;
    int wn = (wid >> 2) * 32;
    int m0 = blockIdx.x * BM, n0 = blockIdx.y * BN;
    int g = lane >> 2, tq = lane & 3;

    float acc[2][4][4];
#pragma unroll
    for (int mt = 0; mt < 2; mt++)
#pragma unroll
        for (int nt = 0; nt < 4; nt++)
#pragma unroll
            for (int j = 0; j < 4; j++) acc[mt][nt][j] = 0.0f;

    for (int k0 = 0; k0 < K; k0 += BK) {
        // A tile: 128 rows x 4 uint4 (8 halves) = 512 slots, 2/thread
#pragma unroll
        for (int i = 0; i < 2; i++) {
            int slot = tid + 256 * i;
            int m = slot >> 2, c8 = slot & 3;
            uint4 raw = make_uint4(0u, 0u, 0u, 0u);
            if (m0 + m < M)
                raw = *(const uint4*)(A + (size_t)(m0 + m) * K + k0 + c8 * 8);
            *(uint4*)&As[m][c8 * 8] = raw;
        }
        // B tile: 64 rows x 4 uint4 = 256 slots, 1/thread
        {
            int n = tid >> 2, c8 = tid & 3;
            uint4 raw = *(const uint4*)(Bt + (size_t)(n0 + n) * K + k0 + c8 * 8);
            *(uint4*)&Bs[n][c8 * 8] = raw;
        }
        __syncthreads();

#pragma unroll
        for (int kk = 0; kk < BK; kk += 16) {
            uint32_t a[2][4], b[4][2];
#pragma unroll
            for (int mt = 0; mt < 2; mt++) {
                int r = wm + mt * 16 + g;
                a[mt][0] = *(const uint32_t*)&As[r][kk + 2 * tq];
                a[mt][1] = *(const uint32_t*)&As[r + 8][kk + 2 * tq];
                a[mt][2] = *(const uint32_t*)&As[r][kk + 2 * tq + 8];
                a[mt][3] = *(const uint32_t*)&As[r + 8][kk + 2 * tq + 8];
            }
#pragma unroll
            for (int nt = 0; nt < 4; nt++) {
                int n = wn + nt * 8 + g;
                b[nt][0] = *(const uint32_t*)&Bs[n][kk + 2 * tq];
                b[nt][1] = *(const uint32_t*)&Bs[n][kk + 2 * tq + 8];
            }
#pragma unroll
            for (int mt = 0; mt < 2; mt++)
#pragma unroll
                for (int nt = 0; nt < 4; nt++)
                    mma_f16(acc[mt][nt], a[mt], b[nt]);
        }
        __syncthreads();
    }

#pragma unroll
    for (int mt = 0; mt < 2; mt++) {
        int row = m0 + wm + mt * 16 + g;
#pragma unroll
        for (int nt = 0; nt < 4; nt++) {
            int col = n0 + wn + nt * 8 + tq * 2;
            if (row < M)
                *(__half2*)(C + (size_t)row * N + col) =
                    __floats2half2_rn(acc[mt][nt][0], acc[mt][nt][1]);
            if (row + 8 < M)
                *(__half2*)(C + (size_t)(row + 8) * N + col) =
                    __floats2half2_rn(acc[mt][nt][2], acc[mt][nt][3]);
        }
    }
}

// ---------------- aggregation (fp16 features, fp32 accumulate) ---------------
__device__ __forceinline__ void h8_fma(float w, uint4 v, float* acc) {
    const __half2* hp = (const __half2*)&v;
#pragma unroll
    for (int i = 0; i < 4; i++) {
        float2 f = __half22float2(hp[i]);
        acc[2 * i]     += w * f.x;
        acc[2 * i + 1] += w * f.y;
    }
}

// 256 channels: warp per node, lane owns 8 channels; 4-edge unroll
__global__ __launch_bounds__(256) void agg256_kernel(
    const __half* __restrict__ h, __half* __restrict__ out,
    const float* __restrict__ bias)
{
    int warp = (blockIdx.x * blockDim.x + threadIdx.x) >> 5;
    int lane = threadIdx.x & 31;
    if (warp >= N_NODES) return;
    int node = warp;

    const uint4* hv = (const uint4*)h;   // 32 uint4 per row
    int p0 = g_ptr[node], p1 = g_ptr[node + 1];
    float dc = g_dinv[node];

    float acc[8];
#pragma unroll
    for (int j = 0; j < 8; j++) acc[j] = 0.0f;
    h8_fma(dc, hv[(size_t)node * 32 + lane], acc);

    int e = p0;
    for (; e + 4 <= p1; e += 4) {
        int s0 = g_csr[e], s1 = g_csr[e + 1], s2 = g_csr[e + 2], s3 = g_csr[e + 3];
        float w0 = g_dinv[s0], w1 = g_dinv[s1], w2 = g_dinv[s2], w3 = g_dinv[s3];
        uint4 v0 = hv[(size_t)s0 * 32 + lane];
        uint4 v1 = hv[(size_t)s1 * 32 + lane];
        uint4 v2 = hv[(size_t)s2 * 32 + lane];
        uint4 v3 = hv[(size_t)s3 * 32 + lane];
        h8_fma(w0, v0, acc);
        h8_fma(w1, v1, acc);
        h8_fma(w2, v2, acc);
        h8_fma(w3, v3, acc);
    }
    for (; e < p1; e++) {
        int s0 = g_csr[e];
        h8_fma(g_dinv[s0], hv[(size_t)s0 * 32 + lane], acc);
    }

    float4 b0 = ((const float4*)bias)[lane * 2];
    float4 b1 = ((const float4*)bias)[lane * 2 + 1];
    float r[8];
    r[0] = fmaxf(dc * acc[0] + b0.x, 0.f);
    r[1] = fmaxf(dc * acc[1] + b0.y, 0.f);
    r[2] = fmaxf(dc * acc[2] + b0.z, 0.f);
    r[3] = fmaxf(dc * acc[3] + b0.w, 0.f);
    r[4] = fmaxf(dc * acc[4] + b1.x, 0.f);
    r[5] = fmaxf(dc * acc[5] + b1.y, 0.f);
    r[6] = fmaxf(dc * acc[6] + b1.z, 0.f);
    r[7] = fmaxf(dc * acc[7] + b1.w, 0.f);

    uint4 o;
    __half2* op = (__half2*)&o;
    op[0] = __floats2half2_rn(r[0], r[1]);
    op[1] = __floats2half2_rn(r[2], r[3]);
    op[2] = __floats2half2_rn(r[4], r[5]);
    op[3] = __floats2half2_rn(r[6], r[7]);
    ((uint4*)out)[(size_t)node * 32 + lane] = o;
}

// 128 channels: HALF-warp per node (16 lanes x uint4 = full 256B row),
// lane owns 8 channels; fp32 output; 4-edge unroll
__global__ __launch_bounds__(256) void agg128_kernel(
    const __half* __restrict__ h, float* __restrict__ out,
    const float* __restrict__ bias)
{
    int gwarp = (blockIdx.x * blockDim.x + threadIdx.x) >> 5;
    int lane = threadIdx.x & 31;
    int node = gwarp * 2 + (lane >> 4);
    int l16 = lane & 15;
    if (node >= N_NODES) return;

    const uint4* hv = (const uint4*)h;   // 16 uint4 per row
    int p0 = g_ptr[node], p1 = g_ptr[node + 1];
    float dc = g_dinv[node];

    float acc[8];
#pragma unroll
    for (int j = 0; j < 8; j++) acc[j] = 0.0f;
    h8_fma(dc, hv[(size_t)node * 16 + l16], acc);

    int e = p0;
    for (; e + 4 <= p1; e += 4) {
        int s0 = g_csr[e], s1 = g_csr[e + 1], s2 = g_csr[e + 2], s3 = g_csr[e + 3];
        float w0 = g_dinv[s0], w1 = g_dinv[s1], w2 = g_dinv[s2], w3 = g_dinv[s3];
        uint4 v0 = hv[(size_t)s0 * 16 + l16];
        uint4 v1 = hv[(size_t)s1 * 16 + l16];
        uint4 v2 = hv[(size_t)s2 * 16 + l16];
        uint4 v3 = hv[(size_t)s3 * 16 + l16];
        h8_fma(w0, v0, acc);
        h8_fma(w1, v1, acc);
        h8_fma(w2, v2, acc);
        h8_fma(w3, v3, acc);
    }
    for (; e < p1; e++) {
        int s0 = g_csr[e];
        h8_fma(g_dinv[s0], hv[(size_t)s0 * 16 + l16], acc);
    }

    float4 b0 = ((const float4*)bias)[l16 * 2];
    float4 b1 = ((const float4*)bias)[l16 * 2 + 1];
    float4 o0, o1;
    o0.x = dc * acc[0] + b0.x;
    o0.y = dc * acc[1] + b0.y;
    o0.z = dc * acc[2] + b0.z;
    o0.w = dc * acc[3] + b0.w;
    o1.x = dc * acc[4] + b1.x;
    o1.y = dc * acc[5] + b1.y;
    o1.z = dc * acc[6] + b1.z;
    o1.w = dc * acc[7] + b1.w;

    float4* ov = (float4*)(out + (size_t)node * 128 + l16 * 8);
    ov[0] = o0;
    ov[1] = o1;
}

// ---------------- launch ------------------------------------------------------
extern "C" void kernel_launch(void* const* d_in, const int* in_sizes, int n_in,
                              void* d_out, int out_size)
{
    const float* x  = (const float*)d_in[0];
    const void*  ei = d_in[1];
    const float* W1 = (const float*)d_in[2];
    const float* b1 = (const float*)d_in[3];
    const float* W2 = (const float*)d_in[4];
    const float* b2 = (const float*)d_in[5];
    float* out = (float*)d_out;

    __half* h1;  cudaGetSymbolAddress((void**)&h1, g_h1);
    __half* a1;  cudaGetSymbolAddress((void**)&a1, g_a1);
    __half* h2;  cudaGetSymbolAddress((void**)&h2, g_h2);
    __half* w2h; cudaGetSymbolAddress((void**)&w2h, g_W2h);

    // dtype detect + CSR build
    detect_kernel<<<1, 256>>>((const unsigned int*)ei);
    zero_kernel<<<(N_NODES + 255) / 256, 256>>>();
    count_kernel<<<(N_EDGES + 255) / 256, 256>>>(ei);
    scan1_kernel<<<NB_SCAN, 256>>>();
    scan2_kernel<<<1, 256>>>();
    scan3_kernel<<<NB_SCAN, 256>>>();
    fill_kernel<<<(N_EDGES + 255) / 256, 256>>>(ei);

    // W2 -> fp16 transposed [N][K]
    transpose_h_kernel<<<dim3(OUT_C / 32, HID_C / 32), dim3(32, 8)>>>(W2, w2h, HID_C, OUT_C);

    int grid_m = (N_NODES + BM - 1) / BM;   // 391
    // layer 1: h1 = x @ W1 (tf32, fp16 out) ; a1 = relu(agg(h1) + b1) (fp16)
    mma_sgemm_kernel<<<dim3(grid_m, HID_C / BN), 256>>>(x, W1, h1, N_NODES, HID_C, IN_C);
    agg256_kernel<<<(N_NODES * 32 + 255) / 256, 256>>>(h1, a1, b1);
    // layer 2: h2 = a1 @ W2 (fp16 mma, fp16 out) ; out = agg(h2) + b2 (fp32)
    mma_hgemm_kernel<<<dim3(grid_m, OUT_C / BN), 256>>>(a1, w2h, h2, N_NODES, OUT_C, HID_C);
    {
        int warps = (N_NODES + 1) / 2;                    // 2 nodes per warp
        agg128_kernel<<<(warps * 32 + 255) / 256, 256>>>(h2, out, b2);
    }
}

// round 6
// speedup vs baseline: 2.5836x; 1.0923x over previous
#include <cuda_runtime.h>
#include <cuda_fp16.h>
#include <cstdint>

#define N_NODES 50000
#define N_EDGES 800000
#define IN_C 256
#define HID_C 256
#define OUT_C 128
#define NB_SCAN ((N_NODES + 255) / 256)

// ---------------- scratch (static device globals; no runtime alloc) ----------
__device__ __align__(256) __half g_h1[N_NODES * HID_C];
__device__ __align__(256) __half g_a1[N_NODES * HID_C];
__device__ __align__(256) __half g_h2[N_NODES * OUT_C];
__device__ __align__(256) __half g_W2h[OUT_C * HID_C];   // W2^T fp16 [N=128][K=256]
__device__ int2  g_csrw[N_EDGES];        // (src, fp32 bits of dinv[src]) grouped by dst
__device__ int   g_ptr[N_NODES + 1];
__device__ int   g_cnt[N_NODES];
__device__ int   g_cur[N_NODES];
__device__ float g_dinv[N_NODES];
__device__ int   g_bsum[256];
__device__ int   g_boff[256];
__device__ int   g_is64;

// ---------------- one-time stream/event infra (host, created at load) --------
struct StreamInit {
    cudaStream_t s2;
    cudaEvent_t evF, evJ;
    StreamInit() {
        cudaStreamCreate(&s2);
        cudaEventCreateWithFlags(&evF, cudaEventDisableTiming);
        cudaEventCreateWithFlags(&evJ, cudaEventDisableTiming);
    }
};
static StreamInit g_si;

// ---------------- zero + dtype detect (merged) --------------------------------
// If edge_index is int64: high words all zero (ids < 50000). int32: nonzero.
__global__ void zero_detect_kernel(const unsigned int* __restrict__ w) {
    int i = blockIdx.x * blockDim.x + threadIdx.x;
    if (i < N_NODES) { g_cnt[i] = 0; g_cur[i] = 0; }
    if (i == 0) g_ptr[N_NODES] = N_EDGES;
    if (blockIdx.x == 0) {
        __shared__ int nz;
        if (threadIdx.x == 0) nz = 0;
        __syncthreads();
        int bad = 0;
        for (int k = threadIdx.x; k < 4096; k += blockDim.x)
            if (w[2 * k + 1] != 0u) bad = 1;
        if (bad) atomicOr(&nz, 1);
        __syncthreads();
        if (threadIdx.x == 0) g_is64 = (nz == 0) ? 1 : 0;
    }
}

__device__ __forceinline__ int edge_at(const void* ei, long long idx) {
    if (g_is64) return (int)((const long long*)ei)[idx];
    return ((const int*)ei)[idx];
}

// ---------------- CSR build --------------------------------------------------
__global__ void count_kernel(const void* __restrict__ ei) {
    int e = blockIdx.x * blockDim.x + threadIdx.x;
    if (e >= N_EDGES) return;
    int c = edge_at(ei, (long long)N_EDGES + e);
    atomicAdd(&g_cnt[c], 1);
}

__global__ void scan1_kernel() {
    int i = blockIdx.x * 256 + threadIdx.x;
    int v = (i < N_NODES) ? g_cnt[i] : 0;
    int lane = threadIdx.x & 31, w = threadIdx.x >> 5;
    for (int o = 16; o; o >>= 1) v += __shfl_down_sync(~0u, v, o);
    __shared__ int ws[8];
    if (!lane) ws[w] = v;
    __syncthreads();
    if (threadIdx.x == 0) {
        int s = 0;
        for (int k = 0; k < 8; k++) s += ws[k];
        g_bsum[blockIdx.x] = s;
    }
}

__global__ void scan2_kernel() {
    int t = threadIdx.x;
    int v = (t < NB_SCAN) ? g_bsum[t] : 0;
    int lane = t & 31, w = t >> 5;
    int x = v;
    for (int o = 1; o < 32; o <<= 1) {
        int y = __shfl_up_sync(~0u, x, o);
        if (lane >= o) x += y;
    }
    __shared__ int ws[8], wo[8];
    if (lane == 31) ws[w] = x;
    __syncthreads();
    if (t == 0) {
        int r = 0;
        for (int k = 0; k < 8; k++) { wo[k] = r; r += ws[k]; }
    }
    __syncthreads();
    if (t < NB_SCAN) g_boff[t] = wo[w] + x - v;
}

__global__ void scan3_kernel() {
    int i = blockIdx.x * 256 + threadIdx.x;
    int c = (i < N_NODES) ? g_cnt[i] : 0;
    int lane = threadIdx.x & 31, w = threadIdx.x >> 5;
    int x = c;
    for (int o = 1; o < 32; o <<= 1) {
        int y = __shfl_up_sync(~0u, x, o);
        if (lane >= o) x += y;
    }
    __shared__ int ws[8], wo[8];
    if (lane == 31) ws[w] = x;
    __syncthreads();
    if (threadIdx.x == 0) {
        int r = 0;
        for (int k = 0; k < 8; k++) { wo[k] = r; r += ws[k]; }
    }
    __syncthreads();
    if (i < N_NODES) {
        g_ptr[i] = g_boff[blockIdx.x] + wo[w] + x - c;
        g_dinv[i] = rsqrtf((float)(c + 1));
    }
}

// fill after scan3: dinv is ready, so fuse the source weight into the record
__global__ void fill_kernel(const void* __restrict__ ei) {
    int e = blockIdx.x * blockDim.x + threadIdx.x;
    if (e >= N_EDGES) return;
    int r = edge_at(ei, e);
    int c = edge_at(ei, (long long)N_EDGES + e);
    int pos = g_ptr[c] + atomicAdd(&g_cur[c], 1);
    g_csrw[pos] = make_int2(r, __float_as_int(g_dinv[r]));
}

// ---------------- W2 transpose+convert: W2h[n][k] = fp16(W2[k][n]) ------------
__global__ void transpose_h_kernel(const float* __restrict__ W, __half* __restrict__ WT,
                                   int Kd, int Nd) {
    __shared__ float t[32][33];
    int bx = blockIdx.x * 32, by = blockIdx.y * 32;
    int x = threadIdx.x, y = threadIdx.y;
#pragma unroll
    for (int j = 0; j < 32; j += 8)
        t[y + j][x] = W[(size_t)(by + y + j) * Nd + bx + x];
    __syncthreads();
#pragma unroll
    for (int j = 0; j < 32; j += 8)
        WT[(size_t)(bx + y + j) * Kd + by + x] = __float2half(t[x][y + j]);
}

// ---------------- GEMM tiling constants ---------------------------------------
#define BM 128
#define BN 64
#define BK 32

// ---------------- TF32 mma.sync GEMM1: C[M,N] = A[M,K] @ B[K,N], fp16 out -----
__device__ __forceinline__ uint32_t tf32_of(float x) {
    uint32_t r;
    asm("cvt.rna.tf32.f32 %0, %1;" : "=r"(r) : "f"(x));
    return r;
}

__device__ __forceinline__ void mma_tf32(float* c, const uint32_t* a, const uint32_t* b) {
    asm volatile(
        "mma.sync.aligned.m16n8k8.row.col.f32.tf32.tf32.f32 "
        "{%0,%1,%2,%3}, {%4,%5,%6,%7}, {%8,%9}, {%0,%1,%2,%3};"
        : "+f"(c[0]), "+f"(c[1]), "+f"(c[2]), "+f"(c[3])
        : "r"(a[0]), "r"(a[1]), "r"(a[2]), "r"(a[3]), "r"(b[0]), "r"(b[1]));
}

__global__ __launch_bounds__(256) void mma_sgemm_kernel(
    const float* __restrict__ A, const float* __restrict__ B,
    __half* __restrict__ C, int M, int N, int K)
{
    __shared__ __align__(16) uint32_t As[BM][BK + 4];
    __shared__ __align__(16) uint32_t Bs[BK][BN + 8];

    int tid = threadIdx.x;
    int lane = tid & 31, wid = tid >> 5;
    int wm = (wid & 3) * 32;
    int wn = (wid >> 2) * 32;
    int m0 = blockIdx.x * BM, n0 = blockIdx.y * BN;
    int g = lane >> 2, tq = lane & 3;

    float acc[2][4][4];
#pragma unroll
    for (int mt = 0; mt < 2; mt++)
#pragma unroll
        for (int nt = 0; nt < 4; nt++)
#pragma unroll
            for (int j = 0; j < 4; j++) acc[mt][nt][j] = 0.0f;

    for (int k0 = 0; k0 < K; k0 += BK) {
#pragma unroll
        for (int i = 0; i < 4; i++) {
            int slot = tid + 256 * i;
            int m = slot >> 3, c4 = slot & 7;
            float4 v = make_float4(0.f, 0.f, 0.f, 0.f);
            if (m0 + m < M)
                v = *(const float4*)(A + (size_t)(m0 + m) * K + k0 + c4 * 4);
            uint4 u = make_uint4(tf32_of(v.x), tf32_of(v.y), tf32_of(v.z), tf32_of(v.w));
            *(uint4*)&As[m][c4 * 4] = u;
        }
#pragma unroll
        for (int i = 0; i < 2; i++) {
            int slot = tid + 256 * i;
            int r = slot >> 4, c4 = slot & 15;
            float4 v = *(const float4*)(B + (size_t)(k0 + r) * N + n0 + c4 * 4);
            uint4 u = make_uint4(tf32_of(v.x), tf32_of(v.y), tf32_of(v.z), tf32_of(v.w));
            *(uint4*)&Bs[r][c4 * 4] = u;
        }
        __syncthreads();

#pragma unroll
        for (int kk = 0; kk < BK; kk += 8) {
            uint32_t a[2][4], b[4][2];
#pragma unroll
            for (int mt = 0; mt < 2; mt++) {
                int r = wm + mt * 16 + g;
                a[mt][0] = As[r][kk + tq];
                a[mt][1] = As[r + 8][kk + tq];
                a[mt][2] = As[r][kk + tq + 4];
                a[mt][3] = As[r + 8][kk + tq + 4];
            }
#pragma unroll
            for (int nt = 0; nt < 4; nt++) {
                int n = wn + nt * 8 + g;
                b[nt][0] = Bs[kk + tq][n];
                b[nt][1] = Bs[kk + tq + 4][n];
            }
#pragma unroll
            for (int mt = 0; mt < 2; mt++)
#pragma unroll
                for (int nt = 0; nt < 4; nt++)
                    mma_tf32(acc[mt][nt], a[mt], b[nt]);
        }
        __syncthreads();
    }

#pragma unroll
    for (int mt = 0; mt < 2; mt++) {
        int row = m0 + wm + mt * 16 + g;
#pragma unroll
        for (int nt = 0; nt < 4; nt++) {
            int col = n0 + wn + nt * 8 + tq * 2;
            if (row < M)
                *(__half2*)(C + (size_t)row * N + col) =
                    __floats2half2_rn(acc[mt][nt][0], acc[mt][nt][1]);
            if (row + 8 < M)
                *(__half2*)(C + (size_t)(row + 8) * N + col) =
                    __floats2half2_rn(acc[mt][nt][2], acc[mt][nt][3]);
        }
    }
}

// ---------------- FP16 mma.sync GEMM2: C[M,N] = A[M,K] @ Bt[N,K]^T ------------
__device__ __forceinline__ void mma_f16(float* c, const uint32_t* a, const uint32_t* b) {
    asm volatile(
        "mma.sync.aligned.m16n8k16.row.col.f32.f16.f16.f32 "
        "{%0,%1,%2,%3}, {%4,%5,%6,%7}, {%8,%9}, {%0,%1,%2,%3};"
        : "+f"(c[0]), "+f"(c[1]), "+f"(c[2]), "+f"(c[3])
        : "r"(a[0]), "r"(a[1]), "r"(a[2]), "r"(a[3]), "r"(b[0]), "r"(b[1]));
}

__global__ __launch_bounds__(256) void mma_hgemm_kernel(
    const __half* __restrict__ A, const __half* __restrict__ Bt,
    __half* __restrict__ C, int M, int N, int K)
{
    __shared__ __align__(16) __half As[BM][BK + 8];
    __shared__ __align__(16) __half Bs[BN][BK + 8];

    int tid = threadIdx.x;
    int lane = tid & 31, wid = tid >> 5;
    int wm = (wid & 3) * 32;
    int wn = (wid >> 2) * 32;
    int m0 = blockIdx.x * BM, n0 = blockIdx.y * BN;
    int g = lane >> 2, tq = lane & 3;

    float acc[2][4][4];
#pragma unroll
    for (int mt = 0; mt < 2; mt++)
#pragma unroll
        for (int nt = 0; nt < 4; nt++)
#pragma unroll
            for (int j = 0; j < 4; j++) acc[mt][nt][j] = 0.0f;

    for (int k0 = 0; k0 < K; k0 += BK) {
#pragma unroll
        for (int i = 0; i < 2; i++) {
            int slot = tid + 256 * i;
            int m = slot >> 2, c8 = slot & 3;
            uint4 raw = make_uint4(0u, 0u, 0u, 0u);
            if (m0 + m < M)
                raw = *(const uint4*)(A + (size_t)(m0 + m) * K + k0 + c8 * 8);
            *(uint4*)&As[m][c8 * 8] = raw;
        }
        {
            int n = tid >> 2, c8 = tid & 3;
            uint4 raw = *(const uint4*)(Bt + (size_t)(n0 + n) * K + k0 + c8 * 8);
            *(uint4*)&Bs[n][c8 * 8] = raw;
        }
        __syncthreads();

#pragma unroll
        for (int kk = 0; kk < BK; kk += 16) {
            uint32_t a[2][4], b[4][2];
#pragma unroll
            for (int mt = 0; mt < 2; mt++) {
                int r = wm + mt * 16 + g;
                a[mt][0] = *(const uint32_t*)&As[r][kk + 2 * tq];
                a[mt][1] = *(const uint32_t*)&As[r + 8][kk + 2 * tq];
                a[mt][2] = *(const uint32_t*)&As[r][kk + 2 * tq + 8];
                a[mt][3] = *(const uint32_t*)&As[r + 8][kk + 2 * tq + 8];
            }
#pragma unroll
            for (int nt = 0; nt < 4; nt++) {
                int n = wn + nt * 8 + g;
                b[nt][0] = *(const uint32_t*)&Bs[n][kk + 2 * tq];
                b[nt][1] = *(const uint32_t*)&Bs[n][kk + 2 * tq + 8];
            }
#pragma unroll
            for (int mt = 0; mt < 2; mt++)
#pragma unroll
                for (int nt = 0; nt < 4; nt++)
                    mma_f16(acc[mt][nt], a[mt], b[nt]);
        }
        __syncthreads();
    }

#pragma unroll
    for (int mt = 0; mt < 2; mt++) {
        int row = m0 + wm + mt * 16 + g;
#pragma unroll
        for (int nt = 0; nt < 4; nt++) {
            int col = n0 + wn + nt * 8 + tq * 2;
            if (row < M)
                *(__half2*)(C + (size_t)row * N + col) =
                    __floats2half2_rn(acc[mt][nt][0], acc[mt][nt][1]);
            if (row + 8 < M)
                *(__half2*)(C + (size_t)(row + 8) * N + col) =
                    __floats2half2_rn(acc[mt][nt][2], acc[mt][nt][3]);
        }
    }
}

// ---------------- aggregation (fp16 features, fp32 accumulate) ---------------
__device__ __forceinline__ void h8_fma(float w, uint4 v, float* acc) {
    const __half2* hp = (const __half2*)&v;
#pragma unroll
    for (int i = 0; i < 4; i++) {
        float2 f = __half22float2(hp[i]);
        acc[2 * i]     += w * f.x;
        acc[2 * i + 1] += w * f.y;
    }
}

// 256 channels: warp per node, lane owns 8 channels; 4-edge unroll, fused weights
__global__ __launch_bounds__(256) void agg256_kernel(
    const __half* __restrict__ h, __half* __restrict__ out,
    const float* __restrict__ bias)
{
    int warp = (blockIdx.x * blockDim.x + threadIdx.x) >> 5;
    int lane = threadIdx.x & 31;
    if (warp >= N_NODES) return;
    int node = warp;

    const uint4* hv = (const uint4*)h;
    int p0 = g_ptr[node], p1 = g_ptr[node + 1];
    float dc = g_dinv[node];

    float acc[8];
#pragma unroll
    for (int j = 0; j < 8; j++) acc[j] = 0.0f;
    h8_fma(dc, hv[(size_t)node * 32 + lane], acc);

    int e = p0;
    for (; e + 4 <= p1; e += 4) {
        int2 c0 = g_csrw[e],     c1 = g_csrw[e + 1];
        int2 c2 = g_csrw[e + 2], c3 = g_csrw[e + 3];
        uint4 v0 = hv[(size_t)c0.x * 32 + lane];
        uint4 v1 = hv[(size_t)c1.x * 32 + lane];
        uint4 v2 = hv[(size_t)c2.x * 32 + lane];
        uint4 v3 = hv[(size_t)c3.x * 32 + lane];
        h8_fma(__int_as_float(c0.y), v0, acc);
        h8_fma(__int_as_float(c1.y), v1, acc);
        h8_fma(__int_as_float(c2.y), v2, acc);
        h8_fma(__int_as_float(c3.y), v3, acc);
    }
    for (; e < p1; e++) {
        int2 c0 = g_csrw[e];
        h8_fma(__int_as_float(c0.y), hv[(size_t)c0.x * 32 + lane], acc);
    }

    float4 b0 = ((const float4*)bias)[lane * 2];
    float4 b1 = ((const float4*)bias)[lane * 2 + 1];
    float r[8];
    r[0] = fmaxf(dc * acc[0] + b0.x, 0.f);
    r[1] = fmaxf(dc * acc[1] + b0.y, 0.f);
    r[2] = fmaxf(dc * acc[2] + b0.z, 0.f);
    r[3] = fmaxf(dc * acc[3] + b0.w, 0.f);
    r[4] = fmaxf(dc * acc[4] + b1.x, 0.f);
    r[5] = fmaxf(dc * acc[5] + b1.y, 0.f);
    r[6] = fmaxf(dc * acc[6] + b1.z, 0.f);
    r[7] = fmaxf(dc * acc[7] + b1.w, 0.f);

    uint4 o;
    __half2* op = (__half2*)&o;
    op[0] = __floats2half2_rn(r[0], r[1]);
    op[1] = __floats2half2_rn(r[2], r[3]);
    op[2] = __floats2half2_rn(r[4], r[5]);
    op[3] = __floats2half2_rn(r[6], r[7]);
    ((uint4*)out)[(size_t)node * 32 + lane] = o;
}

// 128 channels: half-warp per node (16 lanes x uint4 = full row); fp32 out
__global__ __launch_bounds__(256) void agg128_kernel(
    const __half* __restrict__ h, float* __restrict__ out,
    const float* __restrict__ bias)
{
    int gwarp = (blockIdx.x * blockDim.x + threadIdx.x) >> 5;
    int lane = threadIdx.x & 31;
    int node = gwarp * 2 + (lane >> 4);
    int l16 = lane & 15;
    if (node >= N_NODES) return;

    const uint4* hv = (const uint4*)h;
    int p0 = g_ptr[node], p1 = g_ptr[node + 1];
    float dc = g_dinv[node];

    float acc[8];
#pragma unroll
    for (int j = 0; j < 8; j++) acc[j] = 0.0f;
    h8_fma(dc, hv[(size_t)node * 16 + l16], acc);

    int e = p0;
    for (; e + 4 <= p1; e += 4) {
        int2 c0 = g_csrw[e],     c1 = g_csrw[e + 1];
        int2 c2 = g_csrw[e + 2], c3 = g_csrw[e + 3];
        uint4 v0 = hv[(size_t)c0.x * 16 + l16];
        uint4 v1 = hv[(size_t)c1.x * 16 + l16];
        uint4 v2 = hv[(size_t)c2.x * 16 + l16];
        uint4 v3 = hv[(size_t)c3.x * 16 + l16];
        h8_fma(__int_as_float(c0.y), v0, acc);
        h8_fma(__int_as_float(c1.y), v1, acc);
        h8_fma(__int_as_float(c2.y), v2, acc);
        h8_fma(__int_as_float(c3.y), v3, acc);
    }
    for (; e < p1; e++) {
        int2 c0 = g_csrw[e];
        h8_fma(__int_as_float(c0.y), hv[(size_t)c0.x * 16 + l16], acc);
    }

    float4 b0 = ((const float4*)bias)[l16 * 2];
    float4 b1 = ((const float4*)bias)[l16 * 2 + 1];
    float4 o0, o1;
    o0.x = dc * acc[0] + b0.x;
    o0.y = dc * acc[1] + b0.y;
    o0.z = dc * acc[2] + b0.z;
    o0.w = dc * acc[3] + b0.w;
    o1.x = dc * acc[4] + b1.x;
    o1.y = dc * acc[5] + b1.y;
    o1.z = dc * acc[6] + b1.z;
    o1.w = dc * acc[7] + b1.w;

    float4* ov = (float4*)(out + (size_t)node * 128 + l16 * 8);
    ov[0] = o0;
    ov[1] = o1;
}

// ---------------- launch ------------------------------------------------------
extern "C" void kernel_launch(void* const* d_in, const int* in_sizes, int n_in,
                              void* d_out, int out_size)
{
    const float* x  = (const float*)d_in[0];
    const void*  ei = d_in[1];
    const float* W1 = (const float*)d_in[2];
    const float* b1 = (const float*)d_in[3];
    const float* W2 = (const float*)d_in[4];
    const float* b2 = (const float*)d_in[5];
    float* out = (float*)d_out;

    __half* h1;  cudaGetSymbolAddress((void**)&h1, g_h1);
    __half* a1;  cudaGetSymbolAddress((void**)&a1, g_a1);
    __half* h2;  cudaGetSymbolAddress((void**)&h2, g_h2);
    __half* w2h; cudaGetSymbolAddress((void**)&w2h, g_W2h);

    cudaStream_t s0 = 0, s2 = g_si.s2;

    // ---- fork: CSR build on s2, GEMM-side prep+GEMM1 on s0 (parallel) ----
    cudaEventRecord(g_si.evF, s0);
    cudaStreamWaitEvent(s2, g_si.evF, 0);

    // branch A (s2): CSR build
    zero_detect_kernel<<<(N_NODES + 255) / 256, 256, 0, s2>>>((const unsigned int*)ei);
    count_kernel<<<(N_EDGES + 255) / 256, 256, 0, s2>>>(ei);
    scan1_kernel<<<NB_SCAN, 256, 0, s2>>>();
    scan2_kernel<<<1, 256, 0, s2>>>();
    scan3_kernel<<<NB_SCAN, 256, 0, s2>>>();
    fill_kernel<<<(N_EDGES + 255) / 256, 256, 0, s2>>>(ei);
    cudaEventRecord(g_si.evJ, s2);

    // branch B (s0): W2 prep + GEMM1
    transpose_h_kernel<<<dim3(OUT_C / 32, HID_C / 32), dim3(32, 8), 0, s0>>>(
        W2, w2h, HID_C, OUT_C);
    int grid_m = (N_NODES + BM - 1) / BM;   // 391
    mma_sgemm_kernel<<<dim3(grid_m, HID_C / BN), 256, 0, s0>>>(
        x, W1, h1, N_NODES, HID_C, IN_C);

    // ---- join ----
    cudaStreamWaitEvent(s0, g_si.evJ, 0);

    // layer 1 aggregation, layer 2 GEMM + aggregation (serial chain)
    agg256_kernel<<<(N_NODES * 32 + 255) / 256, 256, 0, s0>>>(h1, a1, b1);
    mma_hgemm_kernel<<<dim3(grid_m, OUT_C / BN), 256, 0, s0>>>(
        a1, w2h, h2, N_NODES, OUT_C, HID_C);
    {
        int warps = (N_NODES + 1) / 2;
        agg128_kernel<<<(warps * 32 + 255) / 256, 256, 0, s0>>>(h2, out, b2);
    }
}

// round 7
// speedup vs baseline: 2.7257x; 1.0550x over previous
#include <cuda_runtime.h>
#include <cuda_fp16.h>
#include <cstdint>

#define N_NODES 50000
#define N_EDGES 800000
#define IN_C 256
#define HID_C 256
#define OUT_C 128
#define NB_SCAN ((N_NODES + 255) / 256)
#define CHUNK0 25088                     // 196 blocks of 128 rows

// ---------------- scratch (static device globals; no runtime alloc) ----------
__device__ __align__(256) __half g_h1[N_NODES * HID_C];
__device__ __align__(256) __half g_a1[N_NODES * HID_C];
__device__ __align__(256) __half g_h2[N_NODES * OUT_C];
__device__ __align__(256) __half g_W1h[HID_C * IN_C];    // W1^T fp16 [N=256][K=256]
__device__ __align__(256) __half g_W2h[OUT_C * HID_C];   // W2^T fp16 [N=128][K=256]
__device__ int2  g_csrw[N_EDGES];        // (src, fp32 bits of dinv[src]) grouped by dst
__device__ int   g_ptr[N_NODES + 1];
__device__ int   g_cnt[N_NODES];
__device__ int   g_cur[N_NODES];
__device__ float g_dinv[N_NODES];
__device__ int   g_bsum[256];
__device__ int   g_boff[256];
__device__ int   g_is64;

// ---------------- one-time stream/event infra --------------------------------
struct StreamInit {
    cudaStream_t s2;
    cudaEvent_t evF, evJ, evG1, evB;
    StreamInit() {
        cudaStreamCreate(&s2);
        cudaEventCreateWithFlags(&evF, cudaEventDisableTiming);
        cudaEventCreateWithFlags(&evJ, cudaEventDisableTiming);
        cudaEventCreateWithFlags(&evG1, cudaEventDisableTiming);
        cudaEventCreateWithFlags(&evB, cudaEventDisableTiming);
    }
};
static StreamInit g_si;

// ---------------- zero + dtype detect (merged) --------------------------------
__global__ void zero_detect_kernel(const unsigned int* __restrict__ w) {
    int i = blockIdx.x * blockDim.x + threadIdx.x;
    if (i < N_NODES) { g_cnt[i] = 0; g_cur[i] = 0; }
    if (i == 0) g_ptr[N_NODES] = N_EDGES;
    if (blockIdx.x == 0) {
        __shared__ int nz;
        if (threadIdx.x == 0) nz = 0;
        __syncthreads();
        int bad = 0;
        for (int k = threadIdx.x; k < 4096; k += blockDim.x)
            if (w[2 * k + 1] != 0u) bad = 1;
        if (bad) atomicOr(&nz, 1);
        __syncthreads();
        if (threadIdx.x == 0) g_is64 = (nz == 0) ? 1 : 0;
    }
}

__device__ __forceinline__ int edge_at(const void* ei, long long idx) {
    if (g_is64) return (int)((const long long*)ei)[idx];
    return ((const int*)ei)[idx];
}

// ---------------- CSR build --------------------------------------------------
__global__ void count_kernel(const void* __restrict__ ei) {
    int e = blockIdx.x * blockDim.x + threadIdx.x;
    if (e >= N_EDGES) return;
    int c = edge_at(ei, (long long)N_EDGES + e);
    atomicAdd(&g_cnt[c], 1);
}

__global__ void scan1_kernel() {
    int i = blockIdx.x * 256 + threadIdx.x;
    int v = (i < N_NODES) ? g_cnt[i] : 0;
    int lane = threadIdx.x & 31, w = threadIdx.x >> 5;
    for (int o = 16; o; o >>= 1) v += __shfl_down_sync(~0u, v, o);
    __shared__ int ws[8];
    if (!lane) ws[w] = v;
    __syncthreads();
    if (threadIdx.x == 0) {
        int s = 0;
        for (int k = 0; k < 8; k++) s += ws[k];
        g_bsum[blockIdx.x] = s;
    }
}

__global__ void scan2_kernel() {
    int t = threadIdx.x;
    int v = (t < NB_SCAN) ? g_bsum[t] : 0;
    int lane = t & 31, w = t >> 5;
    int x = v;
    for (int o = 1; o < 32; o <<= 1) {
        int y = __shfl_up_sync(~0u, x, o);
        if (lane >= o) x += y;
    }
    __shared__ int ws[8], wo[8];
    if (lane == 31) ws[w] = x;
    __syncthreads();
    if (t == 0) {
        int r = 0;
        for (int k = 0; k < 8; k++) { wo[k] = r; r += ws[k]; }
    }
    __syncthreads();
    if (t < NB_SCAN) g_boff[t] = wo[w] + x - v;
}

__global__ void scan3_kernel() {
    int i = blockIdx.x * 256 + threadIdx.x;
    int c = (i < N_NODES) ? g_cnt[i] : 0;
    int lane = threadIdx.x & 31, w = threadIdx.x >> 5;
    int x = c;
    for (int o = 1; o < 32; o <<= 1) {
        int y = __shfl_up_sync(~0u, x, o);
        if (lane >= o) x += y;
    }
    __shared__ int ws[8], wo[8];
    if (lane == 31) ws[w] = x;
    __syncthreads();
    if (threadIdx.x == 0) {
        int r = 0;
        for (int k = 0; k < 8; k++) { wo[k] = r; r += ws[k]; }
    }
    __syncthreads();
    if (i < N_NODES) {
        g_ptr[i] = g_boff[blockIdx.x] + wo[w] + x - c;
        g_dinv[i] = rsqrtf((float)(c + 1));
    }
}

__global__ void fill_kernel(const void* __restrict__ ei) {
    int e = blockIdx.x * blockDim.x + threadIdx.x;
    if (e >= N_EDGES) return;
    int r = edge_at(ei, e);
    int c = edge_at(ei, (long long)N_EDGES + e);
    int pos = g_ptr[c] + atomicAdd(&g_cur[c], 1);
    g_csrw[pos] = make_int2(r, __float_as_int(g_dinv[r]));
}

// ---------------- weight transpose+convert: WT[n][k] = fp16(W[k][n]) ----------
__global__ void transpose_h_kernel(const float* __restrict__ W, __half* __restrict__ WT,
                                   int Kd, int Nd) {
    __shared__ float t[32][33];
    int bx = blockIdx.x * 32, by = blockIdx.y * 32;
    int x = threadIdx.x, y = threadIdx.y;
#pragma unroll
    for (int j = 0; j < 32; j += 8)
        t[y + j][x] = W[(size_t)(by + y + j) * Nd + bx + x];
    __syncthreads();
#pragma unroll
    for (int j = 0; j < 32; j += 8)
        WT[(size_t)(bx + y + j) * Kd + by + x] = __float2half(t[x][y + j]);
}

// ---------------- FP16 mma.sync GEMM: C[M,N] = A[M,K] @ Bt[N,K]^T -------------
// A: fp32 (converted at staging) or fp16. Bt fp16 [N][K]. fp32 accum, fp16 out.
#define BM 128
#define BN 64
#define BK 32

__device__ __forceinline__ void mma_f16(float* c, const uint32_t* a, const uint32_t* b) {
    asm volatile(
        "mma.sync.aligned.m16n8k16.row.col.f32.f16.f16.f32 "
        "{%0,%1,%2,%3}, {%4,%5,%6,%7}, {%8,%9}, {%0,%1,%2,%3};"
        : "+f"(c[0]), "+f"(c[1]), "+f"(c[2]), "+f"(c[3])
        : "r"(a[0]), "r"(a[1]), "r"(a[2]), "r"(a[3]), "r"(b[0]), "r"(b[1]));
}

template <typename TA>
__global__ __launch_bounds__(256) void mma_hgemm_kernel(
    const TA* __restrict__ A, const __half* __restrict__ Bt,
    __half* __restrict__ C, int M, int N, int K)
{
    __shared__ __align__(16) __half As[BM][BK + 8];   // rows 80B
    __shared__ __align__(16) __half Bs[BN][BK + 8];

    int tid = threadIdx.x;
    int lane = tid & 31, wid = tid >> 5;
    int wm = (wid & 3) * 32;
    int wn = (wid >> 2) * 32;
    int m0 = blockIdx.x * BM, n0 = blockIdx.y * BN;
    int g = lane >> 2, tq = lane & 3;

    float acc[2][4][4];
#pragma unroll
    for (int mt = 0; mt < 2; mt++)
#pragma unroll
        for (int nt = 0; nt < 4; nt++)
#pragma unroll
            for (int j = 0; j < 4; j++) acc[mt][nt][j] = 0.0f;

    for (int k0 = 0; k0 < K; k0 += BK) {
        if constexpr (sizeof(TA) == 4) {
            // fp32 A: 1024 float4 slots, 4/thread; convert to fp16 at store
#pragma unroll
            for (int i = 0; i < 4; i++) {
                int slot = tid + 256 * i;
                int m = slot >> 3, c4 = slot & 7;
                float4 v = make_float4(0.f, 0.f, 0.f, 0.f);
                if (m0 + m < M)
                    v = *(const float4*)((const float*)A + (size_t)(m0 + m) * K + k0 + c4 * 4);
                uint2 u;
                ((__half2*)&u)[0] = __floats2half2_rn(v.x, v.y);
                ((__half2*)&u)[1] = __floats2half2_rn(v.z, v.w);
                *(uint2*)&As[m][c4 * 4] = u;
            }
        } else {
            // fp16 A: 512 uint4 slots, 2/thread
#pragma unroll
            for (int i = 0; i < 2; i++) {
                int slot = tid + 256 * i;
                int m = slot >> 2, c8 = slot & 3;
                uint4 raw = make_uint4(0u, 0u, 0u, 0u);
                if (m0 + m < M)
                    raw = *(const uint4*)((const __half*)A + (size_t)(m0 + m) * K + k0 + c8 * 8);
                *(uint4*)&As[m][c8 * 8] = raw;
            }
        }
        // B tile: 256 uint4 slots, 1/thread
        {
            int n = tid >> 2, c8 = tid & 3;
            uint4 raw = *(const uint4*)(Bt + (size_t)(n0 + n) * K + k0 + c8 * 8);
            *(uint4*)&Bs[n][c8 * 8] = raw;
        }
        __syncthreads();

#pragma unroll
        for (int kk = 0; kk < BK; kk += 16) {
            uint32_t a[2][4], b[4][2];
#pragma unroll
            for (int mt = 0; mt < 2; mt++) {
                int r = wm + mt * 16 + g;
                a[mt][0] = *(const uint32_t*)&As[r][kk + 2 * tq];
                a[mt][1] = *(const uint32_t*)&As[r + 8][kk + 2 * tq];
                a[mt][2] = *(const uint32_t*)&As[r][kk + 2 * tq + 8];
                a[mt][3] = *(const uint32_t*)&As[r + 8][kk + 2 * tq + 8];
            }
#pragma unroll
            for (int nt = 0; nt < 4; nt++) {
                int n = wn + nt * 8 + g;
                b[nt][0] = *(const uint32_t*)&Bs[n][kk + 2 * tq];
                b[nt][1] = *(const uint32_t*)&Bs[n][kk + 2 * tq + 8];
            }
#pragma unroll
            for (int mt = 0; mt < 2; mt++)
#pragma unroll
                for (int nt = 0; nt < 4; nt++)
                    mma_f16(acc[mt][nt], a[mt], b[nt]);
        }
        __syncthreads();
    }

#pragma unroll
    for (int mt = 0; mt < 2; mt++) {
        int row = m0 + wm + mt * 16 + g;
#pragma unroll
        for (int nt = 0; nt < 4; nt++) {
            int col = n0 + wn + nt * 8 + tq * 2;
            if (row < M)
                *(__half2*)(C + (size_t)row * N + col) =
                    __floats2half2_rn(acc[mt][nt][0], acc[mt][nt][1]);
            if (row + 8 < M)
                *(__half2*)(C + (size_t)(row + 8) * N + col) =
                    __floats2half2_rn(acc[mt][nt][2], acc[mt][nt][3]);
        }
    }
}

// ---------------- aggregation (fp16 features, fp32 accumulate) ---------------
__device__ __forceinline__ void h8_fma(float w, uint4 v, float* acc) {
    const __half2* hp = (const __half2*)&v;
#pragma unroll
    for (int i = 0; i < 4; i++) {
        float2 f = __half22float2(hp[i]);
        acc[2 * i]     += w * f.x;
        acc[2 * i + 1] += w * f.y;
    }
}

// 256 ch: warp per node over [node_base, node_base+node_count)
__global__ __launch_bounds__(256) void agg256_kernel(
    const __half* __restrict__ h, __half* __restrict__ out,
    const float* __restrict__ bias, int node_base, int node_count)
{
    int warp = (blockIdx.x * blockDim.x + threadIdx.x) >> 5;
    int lane = threadIdx.x & 31;
    if (warp >= node_count) return;
    int node = node_base + warp;

    const uint4* hv = (const uint4*)h;
    int p0 = g_ptr[node], p1 = g_ptr[node + 1];
    float dc = g_dinv[node];

    float acc[8];
#pragma unroll
    for (int j = 0; j < 8; j++) acc[j] = 0.0f;
    h8_fma(dc, hv[(size_t)node * 32 + lane], acc);

    int e = p0;
    for (; e + 4 <= p1; e += 4) {
        int2 c0 = g_csrw[e],     c1 = g_csrw[e + 1];
        int2 c2 = g_csrw[e + 2], c3 = g_csrw[e + 3];
        uint4 v0 = hv[(size_t)c0.x * 32 + lane];
        uint4 v1 = hv[(size_t)c1.x * 32 + lane];
        uint4 v2 = hv[(size_t)c2.x * 32 + lane];
        uint4 v3 = hv[(size_t)c3.x * 32 + lane];
        h8_fma(__int_as_float(c0.y), v0, acc);
        h8_fma(__int_as_float(c1.y), v1, acc);
        h8_fma(__int_as_float(c2.y), v2, acc);
        h8_fma(__int_as_float(c3.y), v3, acc);
    }
    for (; e < p1; e++) {
        int2 c0 = g_csrw[e];
        h8_fma(__int_as_float(c0.y), hv[(size_t)c0.x * 32 + lane], acc);
    }

    float4 b0 = ((const float4*)bias)[lane * 2];
    float4 b1 = ((const float4*)bias)[lane * 2 + 1];
    float r[8];
    r[0] = fmaxf(dc * acc[0] + b0.x, 0.f);
    r[1] = fmaxf(dc * acc[1] + b0.y, 0.f);
    r[2] = fmaxf(dc * acc[2] + b0.z, 0.f);
    r[3] = fmaxf(dc * acc[3] + b0.w, 0.f);
    r[4] = fmaxf(dc * acc[4] + b1.x, 0.f);
    r[5] = fmaxf(dc * acc[5] + b1.y, 0.f);
    r[6] = fmaxf(dc * acc[6] + b1.z, 0.f);
    r[7] = fmaxf(dc * acc[7] + b1.w, 0.f);

    uint4 o;
    __half2* op = (__half2*)&o;
    op[0] = __floats2half2_rn(r[0], r[1]);
    op[1] = __floats2half2_rn(r[2], r[3]);
    op[2] = __floats2half2_rn(r[4], r[5]);
    op[3] = __floats2half2_rn(r[6], r[7]);
    ((uint4*)out)[(size_t)node * 32 + lane] = o;
}

// 128 ch: half-warp per node; fp32 out
__global__ __launch_bounds__(256) void agg128_kernel(
    const __half* __restrict__ h, float* __restrict__ out,
    const float* __restrict__ bias)
{
    int gwarp = (blockIdx.x * blockDim.x + threadIdx.x) >> 5;
    int lane = threadIdx.x & 31;
    int node = gwarp * 2 + (lane >> 4);
    int l16 = lane & 15;
    if (node >= N_NODES) return;

    const uint4* hv = (const uint4*)h;
    int p0 = g_ptr[node], p1 = g_ptr[node + 1];
    float dc = g_dinv[node];

    float acc[8];
#pragma unroll
    for (int j = 0; j < 8; j++) acc[j] = 0.0f;
    h8_fma(dc, hv[(size_t)node * 16 + l16], acc);

    int e = p0;
    for (; e + 4 <= p1; e += 4) {
        int2 c0 = g_csrw[e],     c1 = g_csrw[e + 1];
        int2 c2 = g_csrw[e + 2], c3 = g_csrw[e + 3];
        uint4 v0 = hv[(size_t)c0.x * 16 + l16];
        uint4 v1 = hv[(size_t)c1.x * 16 + l16];
        uint4 v2 = hv[(size_t)c2.x * 16 + l16];
        uint4 v3 = hv[(size_t)c3.x * 16 + l16];
        h8_fma(__int_as_float(c0.y), v0, acc);
        h8_fma(__int_as_float(c1.y), v1, acc);
        h8_fma(__int_as_float(c2.y), v2, acc);
        h8_fma(__int_as_float(c3.y), v3, acc);
    }
    for (; e < p1; e++) {
        int2 c0 = g_csrw[e];
        h8_fma(__int_as_float(c0.y), hv[(size_t)c0.x * 16 + l16], acc);
    }

    float4 b0 = ((const float4*)bias)[l16 * 2];
    float4 b1 = ((const float4*)bias)[l16 * 2 + 1];
    float4 o0, o1;
    o0.x = dc * acc[0] + b0.x;
    o0.y = dc * acc[1] + b0.y;
    o0.z = dc * acc[2] + b0.z;
    o0.w = dc * acc[3] + b0.w;
    o1.x = dc * acc[4] + b1.x;
    o1.y = dc * acc[5] + b1.y;
    o1.z = dc * acc[6] + b1.z;
    o1.w = dc * acc[7] + b1.w;

    float4* ov = (float4*)(out + (size_t)node * 128 + l16 * 8);
    ov[0] = o0;
    ov[1] = o1;
}

// ---------------- launch ------------------------------------------------------
extern "C" void kernel_launch(void* const* d_in, const int* in_sizes, int n_in,
                              void* d_out, int out_size)
{
    const float* x  = (const float*)d_in[0];
    const void*  ei = d_in[1];
    const float* W1 = (const float*)d_in[2];
    const float* b1 = (const float*)d_in[3];
    const float* W2 = (const float*)d_in[4];
    const float* b2 = (const float*)d_in[5];
    float* out = (float*)d_out;

    __half* h1;  cudaGetSymbolAddress((void**)&h1, g_h1);
    __half* a1;  cudaGetSymbolAddress((void**)&a1, g_a1);
    __half* h2;  cudaGetSymbolAddress((void**)&h2, g_h2);
    __half* w1h; cudaGetSymbolAddress((void**)&w1h, g_W1h);
    __half* w2h; cudaGetSymbolAddress((void**)&w2h, g_W2h);

    cudaStream_t s0 = 0, s2 = g_si.s2;

    // ---- fork ----
    cudaEventRecord(g_si.evF, s0);
    cudaStreamWaitEvent(s2, g_si.evF, 0);

    // branch A (s2): CSR build
    zero_detect_kernel<<<(N_NODES + 255) / 256, 256, 0, s2>>>((const unsigned int*)ei);
    count_kernel<<<(N_EDGES + 255) / 256, 256, 0, s2>>>(ei);
    scan1_kernel<<<NB_SCAN, 256, 0, s2>>>();
    scan2_kernel<<<1, 256, 0, s2>>>();
    scan3_kernel<<<NB_SCAN, 256, 0, s2>>>();
    fill_kernel<<<(N_EDGES + 255) / 256, 256, 0, s2>>>(ei);
    cudaEventRecord(g_si.evJ, s2);

    // branch B (s0): weight prep + GEMM1 (fp16)
    transpose_h_kernel<<<dim3(HID_C / 32, IN_C / 32), dim3(32, 8), 0, s0>>>(
        W1, w1h, IN_C, HID_C);
    transpose_h_kernel<<<dim3(OUT_C / 32, HID_C / 32), dim3(32, 8), 0, s0>>>(
        W2, w2h, HID_C, OUT_C);
    int grid_m = (N_NODES + BM - 1) / BM;   // 391
    mma_hgemm_kernel<float><<<dim3(grid_m, HID_C / BN), 256, 0, s0>>>(
        x, w1h, h1, N_NODES, HID_C, IN_C);
    cudaEventRecord(g_si.evG1, s0);

    // ---- pipelined layer-1 agg + layer-2 GEMM in two row chunks ----
    const int c1n = N_NODES - CHUNK0;                 // 24912
    // s0: chunk0
    cudaStreamWaitEvent(s0, g_si.evJ, 0);
    agg256_kernel<<<(CHUNK0 * 32 + 255) / 256, 256, 0, s0>>>(h1, a1, b1, 0, CHUNK0);
    mma_hgemm_kernel<__half><<<dim3(CHUNK0 / BM, OUT_C / BN), 256, 0, s0>>>(
        a1, w2h, h2, CHUNK0, OUT_C, HID_C);
    // s2: chunk1 (CSR already in-order on s2; wait for GEMM1)
    cudaStreamWaitEvent(s2, g_si.evG1, 0);
    agg256_kernel<<<(c1n * 32 + 255) / 256, 256, 0, s2>>>(h1, a1, b1, CHUNK0, c1n);
    mma_hgemm_kernel<__half><<<dim3((c1n + BM - 1) / BM, OUT_C / BN), 256, 0, s2>>>(
        a1 + (size_t)CHUNK0 * HID_C, w2h, h2 + (size_t)CHUNK0 * OUT_C,
        c1n, OUT_C, HID_C);
    cudaEventRecord(g_si.evB, s2);

    // ---- join + final aggregation ----
    cudaStreamWaitEvent(s0, g_si.evB, 0);
    {
        int warps = (N_NODES + 1) / 2;
        agg128_kernel<<<(warps * 32 + 255) / 256, 256, 0, s0>>>(h2, out, b2);
    }
}